// round 7
// baseline (speedup 1.0000x reference)
#include <cuda_runtime.h>
#include <cuda_bf16.h>
#include <mma.h>
#include <math.h>
#include <stdint.h>

using namespace nvcuda;

#define B_   4
#define S_   256
#define V_   64
#define LP1_ 11
#define H_   128
#define NH_  8
#define DH_  16
#define NL_  3
#define M_   (B_*S_)   // 1024

// ---------------- scratch (device globals; no allocation) ----------------
__device__ float g_adjT[V_*LP1_*V_];
__device__ __nv_bfloat16 g_zhi [M_*V_*H_];
__device__ __nv_bfloat16 g_zlo [M_*V_*H_];
__device__ __nv_bfloat16 g_z2hi[M_*V_*H_];
__device__ __nv_bfloat16 g_z2lo[M_*V_*H_];
__device__ float g_qkv[3*M_*V_*H_];
__device__ __nv_bfloat16 g_whi[7*V_*H_*H_];
__device__ __nv_bfloat16 g_wlo[7*V_*H_*H_];

// ---------------- split helpers (truncation split, exact hi) --------------
__device__ __forceinline__ void split8(const float* y, uint4& h4, uint4& l4) {
    uint32_t hb[8], lb[8];
    #pragma unroll
    for (int j = 0; j < 8; j++) {
        uint32_t b = __float_as_uint(y[j]);
        float hi = __uint_as_float(b & 0xFFFF0000u);
        hb[j] = b;
        lb[j] = __float_as_uint(y[j] - hi);
    }
    h4 = make_uint4(__byte_perm(hb[0],hb[1],0x7632), __byte_perm(hb[2],hb[3],0x7632),
                    __byte_perm(hb[4],hb[5],0x7632), __byte_perm(hb[6],hb[7],0x7632));
    l4 = make_uint4(__byte_perm(lb[0],lb[1],0x7632), __byte_perm(lb[2],lb[3],0x7632),
                    __byte_perm(lb[4],lb[5],0x7632), __byte_perm(lb[6],lb[7],0x7632));
}
__device__ __forceinline__ void split4(const float* y, uint2& h2, uint2& l2) {
    uint32_t hb[4], lb[4];
    #pragma unroll
    for (int j = 0; j < 4; j++) {
        uint32_t b = __float_as_uint(y[j]);
        float hi = __uint_as_float(b & 0xFFFF0000u);
        hb[j] = b;
        lb[j] = __float_as_uint(y[j] - hi);
    }
    h2 = make_uint2(__byte_perm(hb[0],hb[1],0x7632), __byte_perm(hb[2],hb[3],0x7632));
    l2 = make_uint2(__byte_perm(lb[0],lb[1],0x7632), __byte_perm(lb[2],lb[3],0x7632));
}

__device__ __forceinline__ uint32_t smem_u32(const void* p) {
    uint32_t a;
    asm("{ .reg .u64 t; cvta.to.shared.u64 t, %1; cvt.u32.u64 %0, t; }" : "=r"(a) : "l"(p));
    return a;
}
__device__ __forceinline__ void cpa16(uint32_t dst, const void* src) {
    asm volatile("cp.async.ca.shared.global [%0], [%1], 16;" :: "r"(dst), "l"(src));
}
#define CP_COMMIT() asm volatile("cp.async.commit_group;" ::: "memory")
#define CP_WAIT0()  asm volatile("cp.async.wait_group 0;" ::: "memory")

// ---------------- stage 0: sigmoid + transpose of adjacency --------------
__global__ void prep_adj_kernel(const float* __restrict__ logits, float* __restrict__ adjT) {
    int idx = blockIdx.x * 256 + threadIdx.x;
    if (idx >= V_*V_*LP1_) return;
    int s = idx % V_;
    int r = idx / V_;
    int l = r % LP1_;
    int i = r / LP1_;
    float x = logits[(s*V_ + i)*LP1_ + l];
    adjT[idx] = 1.f / (1.f + __expf(-x));
}

// ---------------- weight split: whi/wlo[(s*V+v)*H*H + k*H + n] ------------
__global__ void prep_w_kernel(const float* __restrict__ mW,
                              const float* __restrict__ Wq, const float* __restrict__ Wk,
                              const float* __restrict__ Wv, const float* __restrict__ Wo,
                              __nv_bfloat16* __restrict__ whi, __nv_bfloat16* __restrict__ wlo) {
    int idx = blockIdx.x * 256 + threadIdx.x;      // one float4
    const int per_mat = H_*H_/4;
    if (idx >= 7*V_*per_mat) return;
    int slotmat = idx / per_mat;
    int within  = idx - slotmat * per_mat;
    int s = slotmat >> 6, v = slotmat & 63;
    const float* src;
    if (s < 3)       src = mW + ((size_t)(v*NL_ + s))*H_*H_;
    else if (s == 3) src = Wq + (size_t)v*H_*H_;
    else if (s == 4) src = Wk + (size_t)v*H_*H_;
    else if (s == 5) src = Wv + (size_t)v*H_*H_;
    else             src = Wo + (size_t)v*H_*H_;
    float4 f = *(const float4*)(src + within*4);
    float y[4] = {f.x, f.y, f.z, f.w};
    uint2 h2, l2;
    split4(y, h2, l2);
    size_t o = (size_t)slotmat*H_*H_ + within*4;
    *(uint2*)(whi + o) = h2;
    *(uint2*)(wlo + o) = l2;
}

// ---------------- stage 1: z[b,t,i,h] (writes bf16 hi/lo) -----------------
__global__ __launch_bounds__(256)
void stage1_kernel(const float* __restrict__ x, const float* __restrict__ adjT,
                   const float* __restrict__ var_emb, const float* __restrict__ temp_emb,
                   __nv_bfloat16* __restrict__ zhi, __nv_bfloat16* __restrict__ zlo) {
    int bt = blockIdx.x;
    int b = bt >> 8;
    int t = bt & 255;
    __shared__ float xw[LP1_][V_];
    __shared__ float Am[V_][V_ + 1];
    __shared__ float Bls[V_][LP1_ + 1];
    int tid = threadIdx.x;

    for (int p = tid; p < LP1_*V_; p += 256) {
        int l = p / V_, s = p % V_;
        int tt = t - l;
        xw[l][s] = (tt >= 0) ? x[((size_t)(b*S_ + tt))*V_ + s] : 0.f;
    }
    __syncthreads();

    for (int p = tid; p < V_*V_; p += 256) {
        int i = p >> 6, s = p & 63;
        const float* ap = adjT + (size_t)i*LP1_*V_ + s;
        float a = 0.f;
        #pragma unroll
        for (int l = 0; l < LP1_; l++) a += xw[l][s] * ap[l*V_];
        Am[i][s] = a;
    }
    for (int p = tid; p < V_*LP1_; p += 256) {
        int i = p / LP1_, l = p % LP1_;
        const float* ap = adjT + ((size_t)i*LP1_ + l)*V_;
        float a = 0.f;
        #pragma unroll 8
        for (int s = 0; s < V_; s++) a += xw[l][s] * ap[s];
        Bls[i][l] = a;
    }
    __syncthreads();

    int tx = tid & 15, ty = tid >> 4;
    float acc[4][8];
    #pragma unroll
    for (int r = 0; r < 4; r++)
        #pragma unroll
        for (int c = 0; c < 8; c++) acc[r][c] = 0.f;

    for (int s = 0; s < V_; s++) {
        float a0 = Am[ty*4+0][s], a1 = Am[ty*4+1][s], a2 = Am[ty*4+2][s], a3 = Am[ty*4+3][s];
        const float4* vp = (const float4*)(var_emb + (size_t)s*H_ + tx*8);
        float4 v0 = vp[0], v1 = vp[1];
        float bv[8] = {v0.x,v0.y,v0.z,v0.w,v1.x,v1.y,v1.z,v1.w};
        #pragma unroll
        for (int c = 0; c < 8; c++) {
            acc[0][c] += a0*bv[c]; acc[1][c] += a1*bv[c];
            acc[2][c] += a2*bv[c]; acc[3][c] += a3*bv[c];
        }
    }
    #pragma unroll
    for (int l = 0; l < LP1_; l++) {
        float a0 = Bls[ty*4+0][l], a1 = Bls[ty*4+1][l], a2 = Bls[ty*4+2][l], a3 = Bls[ty*4+3][l];
        const float4* vp = (const float4*)(temp_emb + (size_t)l*H_ + tx*8);
        float4 v0 = vp[0], v1 = vp[1];
        float bv[8] = {v0.x,v0.y,v0.z,v0.w,v1.x,v1.y,v1.z,v1.w};
        #pragma unroll
        for (int c = 0; c < 8; c++) {
            acc[0][c] += a0*bv[c]; acc[1][c] += a1*bv[c];
            acc[2][c] += a2*bv[c]; acc[3][c] += a3*bv[c];
        }
    }
    #pragma unroll
    for (int r = 0; r < 4; r++) {
        int i = ty*4 + r;
        size_t o = ((size_t)bt*V_ + i)*H_ + tx*8;
        uint4 h4, l4;
        split8(acc[r], h4, l4);
        *(uint4*)(zhi + o) = h4;
        *(uint4*)(zlo + o) = l4;
    }
}

// ============= wmma bf16-split GEMM: 64x128 tile, K-chunk 64, 4 CTA/SM =====
#define OFF_P0   0
#define OFF_P1   512
#define OFF_P2   1024
#define OFF_T    2048
#define LDA      72
#define LDB      136
#define SA_HI    (OFF_T)
#define SA_LO    (SA_HI + 64*LDA*2)       // +9216
#define SB_HI    (SA_LO + 64*LDA*2)       // +9216
#define SB_LO    (SB_HI + 64*LDB*2)       // +17408
#define GSM_TOTAL (SB_LO + 64*LDB*2)      // 55296 B
#define OFF_C    OFF_T
#define LDC      132

// MODE 0: out = D (QKV via blockIdx.z; biases folded into attn)
// MODE 1: outHi/Lo = split(GELU(LN(D+bias)*g+b))
// MODE 2: outF[m,v] = (D + bias) . oW + oB
template <int MODE>
__global__ __launch_bounds__(256, 4)
void vgemm_wmma(const __nv_bfloat16* __restrict__ Ahi, const __nv_bfloat16* __restrict__ Alo,
                const __nv_bfloat16* __restrict__ Whi, const __nv_bfloat16* __restrict__ Wlo,
                const float* __restrict__ b0,
                const float* __restrict__ lng, const float* __restrict__ lnb,
                const float* __restrict__ oW, const float* __restrict__ oB,
                float* __restrict__ outF,
                __nv_bfloat16* __restrict__ outHi, __nv_bfloat16* __restrict__ outLo,
                int b_vs) {
    extern __shared__ char smem[];
    uint32_t sbase = smem_u32(smem);
    int tid = threadIdx.x;
    int v = blockIdx.y, m0 = blockIdx.x * 64;

    size_t wofs = (size_t)v * H_ * H_;
    if (MODE == 0) {
        int zi = blockIdx.z;
        wofs += (size_t)zi * V_ * H_ * H_;
        outF += (size_t)zi * M_ * V_ * H_;
    }

    float* sBias = (float*)(smem + OFF_P0);
    float* sG    = (float*)(smem + OFF_P1);
    float* sBeta = (float*)(smem + OFF_P2);
    if (MODE != 0 && tid < 128) {
        sBias[tid] = b0[(size_t)v*b_vs + tid];
        if (MODE == 1) {
            sG[tid]    = lng[(size_t)v*b_vs + tid];
            sBeta[tid] = lnb[(size_t)v*b_vs + tid];
        } else {
            sG[tid] = oW[(size_t)v*H_ + tid];
        }
    }

    int w = tid >> 5;
    int wm = w & 1;        // 2 warps over M (32 rows)
    int wn = w >> 1;       // 4 warps over N (32 cols)

    wmma::fragment<wmma::accumulator, 16, 16, 16, float> acc[2][2];
    #pragma unroll
    for (int mi = 0; mi < 2; mi++)
        #pragma unroll
        for (int ni = 0; ni < 2; ni++) wmma::fill_fragment(acc[mi][ni], 0.f);

    const __nv_bfloat16* aHi = (const __nv_bfloat16*)(smem + SA_HI);
    const __nv_bfloat16* aLo = (const __nv_bfloat16*)(smem + SA_LO);
    const __nv_bfloat16* bHi = (const __nv_bfloat16*)(smem + SB_HI);
    const __nv_bfloat16* bLo = (const __nv_bfloat16*)(smem + SB_LO);

    const size_t arow = (size_t)V_ * H_;
    const size_t abase = (size_t)m0 * arow + (size_t)v * H_;

    #pragma unroll
    for (int ch = 0; ch < 2; ch++) {
        if (ch) __syncthreads();
        // A chunk: 64 rows x 64 k (hi + lo), cp.async
        #pragma unroll
        for (int i = 0; i < 2; i++) {
            int f = tid + 256*i;
            int row = f >> 3, seg = f & 7;
            uint32_t so = (uint32_t)row*(LDA*2) + seg*16;
            size_t go = abase + (size_t)row*arow + ch*64 + seg*8;
            cpa16(sbase + SA_HI + so, Ahi + go);
            cpa16(sbase + SA_LO + so, Alo + go);
        }
        // B chunk: 64 k-rows x 128 n (hi + lo)
        #pragma unroll
        for (int i = 0; i < 4; i++) {
            int f = tid + 256*i;
            int row = f >> 4, seg = f & 15;
            uint32_t so = (uint32_t)row*(LDB*2) + seg*16;
            size_t go = wofs + (size_t)(ch*64 + row)*H_ + seg*8;
            cpa16(sbase + SB_HI + so, Whi + go);
            cpa16(sbase + SB_LO + so, Wlo + go);
        }
        CP_COMMIT();
        CP_WAIT0();
        __syncthreads();

        #pragma unroll
        for (int p = 0; p < 3; p++) {
            const __nv_bfloat16* aS = (p == 2) ? aLo : aHi;
            const __nv_bfloat16* bS = (p == 1) ? bLo : bHi;
            #pragma unroll
            for (int k0 = 0; k0 < 4; k0++) {
                int k = k0 * 16;
                wmma::fragment<wmma::matrix_a, 16, 16, 16, __nv_bfloat16, wmma::row_major> af[2];
                wmma::fragment<wmma::matrix_b, 16, 16, 16, __nv_bfloat16, wmma::row_major> bf[2];
                #pragma unroll
                for (int mi = 0; mi < 2; mi++)
                    wmma::load_matrix_sync(af[mi], aS + (size_t)(wm*32 + mi*16)*LDA + k, LDA);
                #pragma unroll
                for (int ni = 0; ni < 2; ni++)
                    wmma::load_matrix_sync(bf[ni], bS + (size_t)k*LDB + wn*32 + ni*16, LDB);
                #pragma unroll
                for (int mi = 0; mi < 2; mi++)
                    #pragma unroll
                    for (int ni = 0; ni < 2; ni++)
                        wmma::mma_sync(acc[mi][ni], af[mi], bf[ni], acc[mi][ni]);
            }
        }
    }

    if constexpr (MODE == 0) {
        #pragma unroll
        for (int mi = 0; mi < 2; mi++)
            #pragma unroll
            for (int ni = 0; ni < 2; ni++)
                wmma::store_matrix_sync(
                    outF + ((size_t)(m0 + wm*32 + mi*16)*V_ + v)*H_ + wn*32 + ni*16,
                    acc[mi][ni], (unsigned)(V_*H_), wmma::mem_row_major);
        return;
    }

    __syncthreads();
    float* Cs = (float*)(smem + OFF_C);
    #pragma unroll
    for (int mi = 0; mi < 2; mi++)
        #pragma unroll
        for (int ni = 0; ni < 2; ni++)
            wmma::store_matrix_sync(Cs + (size_t)(wm*32 + mi*16)*LDC + wn*32 + ni*16,
                                    acc[mi][ni], LDC, wmma::mem_row_major);
    __syncthreads();

    // ---- epilogue: thread owns a quarter row (32 cols) ----
    int row = tid >> 2, qt = tid & 3;
    const float* crow = Cs + (size_t)row*LDC + qt*32;
    const float* bcol = sBias + qt*32;
    int grow = m0 + row;

    if constexpr (MODE == 1) {
        float s = 0.f, q = 0.f;
        #pragma unroll
        for (int c = 0; c < 32; c += 4) {
            float4 cc = *(const float4*)(crow + c);
            float4 bb = *(const float4*)(bcol + c);
            float y0 = cc.x+bb.x, y1 = cc.y+bb.y, y2 = cc.z+bb.z, y3 = cc.w+bb.w;
            s += y0 + y1 + y2 + y3;
            q += y0*y0 + y1*y1 + y2*y2 + y3*y3;
        }
        s += __shfl_xor_sync(0xFFFFFFFFu, s, 1);
        q += __shfl_xor_sync(0xFFFFFFFFu, q, 1);
        s += __shfl_xor_sync(0xFFFFFFFFu, s, 2);
        q += __shfl_xor_sync(0xFFFFFFFFu, q, 2);
        float mean = s * (1.f/128.f);
        float var  = q * (1.f/128.f) - mean*mean;
        float rstd = rsqrtf(var + 1e-5f);
        size_t obase = ((size_t)grow*V_ + v)*H_ + qt*32;
        const float* gcol = sG + qt*32;
        const float* lcol = sBeta + qt*32;
        #pragma unroll
        for (int c = 0; c < 32; c += 8) {
            float o8[8];
            #pragma unroll
            for (int j = 0; j < 8; j += 4) {
                float4 cc = *(const float4*)(crow + c + j);
                float4 bb = *(const float4*)(bcol + c + j);
                float4 gg = *(const float4*)(gcol + c + j);
                float4 ll = *(const float4*)(lcol + c + j);
                float yv[4] = {cc.x+bb.x, cc.y+bb.y, cc.z+bb.z, cc.w+bb.w};
                float gv[4] = {gg.x, gg.y, gg.z, gg.w};
                float lv[4] = {ll.x, ll.y, ll.z, ll.w};
                #pragma unroll
                for (int u = 0; u < 4; u++) {
                    float t2 = (yv[u] - mean) * rstd * gv[u] + lv[u];
                    o8[j+u] = 0.5f * t2 * (1.f + erff(t2 * 0.7071067811865476f));
                }
            }
            uint4 h4, l4;
            split8(o8, h4, l4);
            *(uint4*)(outHi + obase + c) = h4;
            *(uint4*)(outLo + obase + c) = l4;
        }
    } else {  // MODE 2
        const float* gcol = sG + qt*32;
        float p = 0.f;
        #pragma unroll
        for (int c = 0; c < 32; c += 4) {
            float4 cc = *(const float4*)(crow + c);
            float4 bb = *(const float4*)(bcol + c);
            float4 gg = *(const float4*)(gcol + c);
            p += (cc.x+bb.x)*gg.x + (cc.y+bb.y)*gg.y + (cc.z+bb.z)*gg.z + (cc.w+bb.w)*gg.w;
        }
        p += __shfl_xor_sync(0xFFFFFFFFu, p, 1);
        p += __shfl_xor_sync(0xFFFFFFFFu, p, 2);
        if (qt == 0)
            outF[(size_t)grow*V_ + v] = p + oB[v];
    }
}

// ---------------- attention (adds q/k/v biases; writes bf16 hi/lo) --------
__global__ __launch_bounds__(256)
void attn_kernel(const float* __restrict__ qkv,
                 const float* __restrict__ bq, const float* __restrict__ bk,
                 const float* __restrict__ bv,
                 __nv_bfloat16* __restrict__ ohi, __nv_bfloat16* __restrict__ olo) {
    int bid = blockIdx.x;
    int n = bid & 7;
    int v = (bid >> 3) & 63;
    int b = bid >> 9;
    __shared__ float Ks[S_][DH_];
    __shared__ float Vs[S_][DH_];
    int t = threadIdx.x;

    const float* q  = qkv;
    const float* k  = qkv + (size_t)M_*V_*H_;
    const float* vv = qkv + (size_t)2*M_*V_*H_;

    size_t rowstride = (size_t)V_ * H_;
    size_t base = ((size_t)(b*S_)*V_ + v)*H_ + n*DH_;
    size_t bofs = (size_t)v*H_ + n*DH_;

    float4 bk0 = *(const float4*)(bk + bofs),     bk1 = *(const float4*)(bk + bofs + 4);
    float4 bk2 = *(const float4*)(bk + bofs + 8), bk3 = *(const float4*)(bk + bofs + 12);
    float4 bv0 = *(const float4*)(bv + bofs),     bv1 = *(const float4*)(bv + bofs + 4);
    float4 bv2 = *(const float4*)(bv + bofs + 8), bv3 = *(const float4*)(bv + bofs + 12);
    {
        const float4* kp = (const float4*)(k  + base + (size_t)t*rowstride);
        const float4* vp = (const float4*)(vv + base + (size_t)t*rowstride);
        float4 k0 = kp[0], k1 = kp[1], k2 = kp[2], k3 = kp[3];
        float4 w0 = vp[0], w1 = vp[1], w2 = vp[2], w3 = vp[3];
        k0.x+=bk0.x; k0.y+=bk0.y; k0.z+=bk0.z; k0.w+=bk0.w;
        k1.x+=bk1.x; k1.y+=bk1.y; k1.z+=bk1.z; k1.w+=bk1.w;
        k2.x+=bk2.x; k2.y+=bk2.y; k2.z+=bk2.z; k2.w+=bk2.w;
        k3.x+=bk3.x; k3.y+=bk3.y; k3.z+=bk3.z; k3.w+=bk3.w;
        w0.x+=bv0.x; w0.y+=bv0.y; w0.z+=bv0.z; w0.w+=bv0.w;
        w1.x+=bv1.x; w1.y+=bv1.y; w1.z+=bv1.z; w1.w+=bv1.w;
        w2.x+=bv2.x; w2.y+=bv2.y; w2.z+=bv2.z; w2.w+=bv2.w;
        w3.x+=bv3.x; w3.y+=bv3.y; w3.z+=bv3.z; w3.w+=bv3.w;
        *(float4*)&Ks[t][0]  = k0; *(float4*)&Ks[t][4]  = k1;
        *(float4*)&Ks[t][8]  = k2; *(float4*)&Ks[t][12] = k3;
        *(float4*)&Vs[t][0]  = w0; *(float4*)&Vs[t][4]  = w1;
        *(float4*)&Vs[t][8]  = w2; *(float4*)&Vs[t][12] = w3;
    }
    float4 q0, q1, q2, q3;
    {
        const float4* qp = (const float4*)(q + base + (size_t)t*rowstride);
        float4 a0 = *(const float4*)(bq + bofs),     a1 = *(const float4*)(bq + bofs + 4);
        float4 a2 = *(const float4*)(bq + bofs + 8), a3 = *(const float4*)(bq + bofs + 12);
        q0 = qp[0]; q1 = qp[1]; q2 = qp[2]; q3 = qp[3];
        q0.x+=a0.x; q0.y+=a0.y; q0.z+=a0.z; q0.w+=a0.w;
        q1.x+=a1.x; q1.y+=a1.y; q1.z+=a1.z; q1.w+=a1.w;
        q2.x+=a2.x; q2.y+=a2.y; q2.z+=a2.z; q2.w+=a2.w;
        q3.x+=a3.x; q3.y+=a3.y; q3.z+=a3.z; q3.w+=a3.w;
    }
    __syncthreads();

    float m = -1e30f, ssum = 0.f;
    float av[16];
    #pragma unroll
    for (int d = 0; d < 16; d++) av[d] = 0.f;

    for (int j = 0; j < S_; j++) {
        float4 k0 = *(float4*)&Ks[j][0],  k1 = *(float4*)&Ks[j][4];
        float4 k2 = *(float4*)&Ks[j][8],  k3 = *(float4*)&Ks[j][12];
        float s = q0.x*k0.x + q0.y*k0.y + q0.z*k0.z + q0.w*k0.w
                + q1.x*k1.x + q1.y*k1.y + q1.z*k1.z + q1.w*k1.w
                + q2.x*k2.x + q2.y*k2.y + q2.z*k2.z + q2.w*k2.w
                + q3.x*k3.x + q3.y*k3.y + q3.z*k3.z + q3.w*k3.w;
        s *= 0.25f;
        if (s > m) {
            float corr = __expf(m - s);
            ssum *= corr;
            #pragma unroll
            for (int d = 0; d < 16; d++) av[d] *= corr;
            m = s;
        }
        float e = __expf(s - m);
        ssum += e;
        float4 w0 = *(float4*)&Vs[j][0],  w1 = *(float4*)&Vs[j][4];
        float4 w2 = *(float4*)&Vs[j][8],  w3 = *(float4*)&Vs[j][12];
        av[0]  += e*w0.x; av[1]  += e*w0.y; av[2]  += e*w0.z; av[3]  += e*w0.w;
        av[4]  += e*w1.x; av[5]  += e*w1.y; av[6]  += e*w1.z; av[7]  += e*w1.w;
        av[8]  += e*w2.x; av[9]  += e*w2.y; av[10] += e*w2.z; av[11] += e*w2.w;
        av[12] += e*w3.x; av[13] += e*w3.y; av[14] += e*w3.z; av[15] += e*w3.w;
    }
    float inv = 1.f / ssum;
    #pragma unroll
    for (int d = 0; d < 16; d++) av[d] *= inv;
    uint4 h0, l0, h1, l1;
    split8(av,     h0, l0);
    split8(av + 8, h1, l1);
    size_t o = base + (size_t)t*rowstride;
    *(uint4*)(ohi + o)     = h0;
    *(uint4*)(ohi + o + 8) = h1;
    *(uint4*)(olo + o)     = l0;
    *(uint4*)(olo + o + 8) = l1;
}

// ---------------- launch ---------------------------------------------------
extern "C" void kernel_launch(void* const* d_in, const int* in_sizes, int n_in,
                              void* d_out, int out_size) {
    const float* x       = (const float*)d_in[0];
    const float* adjlog  = (const float*)d_in[1];
    const float* var_emb = (const float*)d_in[2];
    const float* temp_emb= (const float*)d_in[3];
    const float* mech_W  = (const float*)d_in[4];
    const float* mech_b  = (const float*)d_in[5];
    const float* ln_g    = (const float*)d_in[6];
    const float* ln_b    = (const float*)d_in[7];
    const float* Wq      = (const float*)d_in[8];
    const float* Wk      = (const float*)d_in[9];
    const float* Wv      = (const float*)d_in[10];
    const float* Wo      = (const float*)d_in[11];
    const float* bq      = (const float*)d_in[12];
    const float* bk      = (const float*)d_in[13];
    const float* bv      = (const float*)d_in[14];
    const float* bo      = (const float*)d_in[15];
    const float* out_W   = (const float*)d_in[16];
    const float* out_b   = (const float*)d_in[17];
    float* out = (float*)d_out;

    float *adjT, *qkv;
    __nv_bfloat16 *zhi, *zlo, *z2hi, *z2lo, *whi, *wlo;
    cudaGetSymbolAddress((void**)&adjT, g_adjT);
    cudaGetSymbolAddress((void**)&zhi,  g_zhi);
    cudaGetSymbolAddress((void**)&zlo,  g_zlo);
    cudaGetSymbolAddress((void**)&z2hi, g_z2hi);
    cudaGetSymbolAddress((void**)&z2lo, g_z2lo);
    cudaGetSymbolAddress((void**)&qkv,  g_qkv);
    cudaGetSymbolAddress((void**)&whi,  g_whi);
    cudaGetSymbolAddress((void**)&wlo,  g_wlo);

    cudaFuncSetAttribute(vgemm_wmma<0>, cudaFuncAttributeMaxDynamicSharedMemorySize, GSM_TOTAL);
    cudaFuncSetAttribute(vgemm_wmma<1>, cudaFuncAttributeMaxDynamicSharedMemorySize, GSM_TOTAL);
    cudaFuncSetAttribute(vgemm_wmma<2>, cudaFuncAttributeMaxDynamicSharedMemorySize, GSM_TOTAL);

    prep_adj_kernel<<<(V_*V_*LP1_ + 255)/256, 256>>>(adjlog, adjT);
    prep_w_kernel<<<(7*V_*H_*H_/4 + 255)/256, 256>>>(mech_W, Wq, Wk, Wv, Wo, whi, wlo);
    stage1_kernel<<<M_, 256>>>(x, adjT, var_emb, temp_emb, zhi, zlo);

    size_t slot = (size_t)V_*H_*H_;
    dim3 gg(M_/64, V_);
    // mech layers (ping-pong z <-> z2), slots 0..2
    vgemm_wmma<1><<<gg, 256, GSM_TOTAL>>>(zhi, zlo, whi + 0*slot, wlo + 0*slot,
                                          mech_b + 0*H_, ln_g + 0*H_, ln_b + 0*H_,
                                          nullptr, nullptr, nullptr, z2hi, z2lo, NL_*H_);
    vgemm_wmma<1><<<gg, 256, GSM_TOTAL>>>(z2hi, z2lo, whi + 1*slot, wlo + 1*slot,
                                          mech_b + 1*H_, ln_g + 1*H_, ln_b + 1*H_,
                                          nullptr, nullptr, nullptr, zhi, zlo, NL_*H_);
    vgemm_wmma<1><<<gg, 256, GSM_TOTAL>>>(zhi, zlo, whi + 2*slot, wlo + 2*slot,
                                          mech_b + 2*H_, ln_g + 2*H_, ln_b + 2*H_,
                                          nullptr, nullptr, nullptr, z2hi, z2lo, NL_*H_);
    // fused QKV: slots 3..5 via blockIdx.z; fp32 direct store
    dim3 gq(M_/64, V_, 3);
    vgemm_wmma<0><<<gq, 256, GSM_TOTAL>>>(z2hi, z2lo, whi + 3*slot, wlo + 3*slot,
                                          nullptr, nullptr, nullptr, nullptr, nullptr,
                                          qkv, nullptr, nullptr, H_);
    // attention -> bf16 hi/lo into z buffers (free after mech3)
    attn_kernel<<<B_*V_*NH_, 256>>>(qkv, bq, bk, bv, zhi, zlo);
    // O-proj + output head fused, slot 6
    vgemm_wmma<2><<<gg, 256, GSM_TOTAL>>>(zhi, zlo, whi + 6*slot, wlo + 6*slot,
                                          bo, nullptr, nullptr, out_W, out_b,
                                          out, nullptr, nullptr, H_);
}

// round 8
// speedup vs baseline: 1.5312x; 1.5312x over previous
#include <cuda_runtime.h>
#include <cuda_bf16.h>
#include <mma.h>
#include <math.h>
#include <stdint.h>

using namespace nvcuda;

#define B_   4
#define S_   256
#define V_   64
#define LP1_ 11
#define H_   128
#define NH_  8
#define DH_  16
#define NL_  3
#define M_   (B_*S_)   // 1024

// ---------------- scratch (device globals; no allocation) ----------------
__device__ float g_adjT[V_*LP1_*V_];
__device__ float g_z [M_*V_*H_];
__device__ float g_z2[M_*V_*H_];
__device__ float g_qkv[3*M_*V_*H_];

// ---------------- bf16 pack helpers --------------------------------------
__device__ __forceinline__ uint32_t pkrn(float x, float y) {
    __nv_bfloat162 h = __floats2bfloat162_rn(x, y);
    return *(uint32_t*)&h;
}
__device__ __forceinline__ uint32_t pklo(float x, float y, uint32_t hi) {
    __nv_bfloat162 h = *(__nv_bfloat162*)&hi;
    return pkrn(x - __bfloat162float(h.x), y - __bfloat162float(h.y));
}

// mma.sync m16n8k16 row.col bf16 -> f32 accumulate in place
__device__ __forceinline__ void mma16816(float* c, const uint32_t* a, uint32_t b0, uint32_t b1) {
    asm volatile(
        "mma.sync.aligned.m16n8k16.row.col.f32.bf16.bf16.f32 "
        "{%0,%1,%2,%3}, {%4,%5,%6,%7}, {%8,%9}, {%0,%1,%2,%3};\n"
        : "+f"(c[0]), "+f"(c[1]), "+f"(c[2]), "+f"(c[3])
        : "r"(a[0]), "r"(a[1]), "r"(a[2]), "r"(a[3]), "r"(b0), "r"(b1));
}

// ---------------- stage 0: sigmoid + transpose of adjacency --------------
__global__ void prep_adj_kernel(const float* __restrict__ logits, float* __restrict__ adjT) {
    int idx = blockIdx.x * 256 + threadIdx.x;
    if (idx >= V_*V_*LP1_) return;
    int s = idx % V_;
    int r = idx / V_;
    int l = r % LP1_;
    int i = r / LP1_;
    float x = logits[(s*V_ + i)*LP1_ + l];
    adjT[idx] = 1.f / (1.f + __expf(-x));
}

// ---------------- stage 1: z[b,t,i,h] -------------------------------------
__global__ __launch_bounds__(256)
void stage1_kernel(const float* __restrict__ x, const float* __restrict__ adjT,
                   const float* __restrict__ var_emb, const float* __restrict__ temp_emb,
                   float* __restrict__ z) {
    int bt = blockIdx.x;
    int b = bt >> 8;
    int t = bt & 255;
    __shared__ float xw[LP1_][V_];
    __shared__ float Am[V_][V_ + 1];
    __shared__ float Bls[V_][LP1_ + 1];
    int tid = threadIdx.x;

    for (int p = tid; p < LP1_*V_; p += 256) {
        int l = p / V_, s = p % V_;
        int tt = t - l;
        xw[l][s] = (tt >= 0) ? x[((size_t)(b*S_ + tt))*V_ + s] : 0.f;
    }
    __syncthreads();

    for (int p = tid; p < V_*V_; p += 256) {
        int i = p >> 6, s = p & 63;
        const float* ap = adjT + (size_t)i*LP1_*V_ + s;
        float a = 0.f;
        #pragma unroll
        for (int l = 0; l < LP1_; l++) a += xw[l][s] * ap[l*V_];
        Am[i][s] = a;
    }
    for (int p = tid; p < V_*LP1_; p += 256) {
        int i = p / LP1_, l = p % LP1_;
        const float* ap = adjT + ((size_t)i*LP1_ + l)*V_;
        float a = 0.f;
        #pragma unroll 8
        for (int s = 0; s < V_; s++) a += xw[l][s] * ap[s];
        Bls[i][l] = a;
    }
    __syncthreads();

    int tx = tid & 15, ty = tid >> 4;
    float acc[4][8];
    #pragma unroll
    for (int r = 0; r < 4; r++)
        #pragma unroll
        for (int c = 0; c < 8; c++) acc[r][c] = 0.f;

    for (int s = 0; s < V_; s++) {
        float a0 = Am[ty*4+0][s], a1 = Am[ty*4+1][s], a2 = Am[ty*4+2][s], a3 = Am[ty*4+3][s];
        const float4* vp = (const float4*)(var_emb + (size_t)s*H_ + tx*8);
        float4 v0 = vp[0], v1 = vp[1];
        float bv[8] = {v0.x,v0.y,v0.z,v0.w,v1.x,v1.y,v1.z,v1.w};
        #pragma unroll
        for (int c = 0; c < 8; c++) {
            acc[0][c] += a0*bv[c]; acc[1][c] += a1*bv[c];
            acc[2][c] += a2*bv[c]; acc[3][c] += a3*bv[c];
        }
    }
    #pragma unroll
    for (int l = 0; l < LP1_; l++) {
        float a0 = Bls[ty*4+0][l], a1 = Bls[ty*4+1][l], a2 = Bls[ty*4+2][l], a3 = Bls[ty*4+3][l];
        const float4* vp = (const float4*)(temp_emb + (size_t)l*H_ + tx*8);
        float4 v0 = vp[0], v1 = vp[1];
        float bv[8] = {v0.x,v0.y,v0.z,v0.w,v1.x,v1.y,v1.z,v1.w};
        #pragma unroll
        for (int c = 0; c < 8; c++) {
            acc[0][c] += a0*bv[c]; acc[1][c] += a1*bv[c];
            acc[2][c] += a2*bv[c]; acc[3][c] += a3*bv[c];
        }
    }
    #pragma unroll
    for (int r = 0; r < 4; r++) {
        int i = ty*4 + r;
        float* zp = z + ((size_t)bt*V_ + i)*H_ + tx*8;
        *(float4*)(zp)   = make_float4(acc[r][0], acc[r][1], acc[r][2], acc[r][3]);
        *(float4*)(zp+4) = make_float4(acc[r][4], acc[r][5], acc[r][6], acc[r][7]);
    }
}

// ============= wmma bf16-split GEMM: 128x128 tile, K-chunk 64, 2 CTA/SM ====
#define OFF_P0   0
#define OFF_P1   512
#define OFF_P2   1024
#define OFF_T    2048
#define LDA      72
#define LDB      136
#define A_TILE_B (128*LDA*2)   // 18432
#define B_TILE_B (64*LDB*2)    // 17408
#define OFF_AHI  (OFF_T)
#define OFF_ALO  (OFF_AHI + A_TILE_B)
#define OFF_BHI  (OFF_ALO + A_TILE_B)
#define OFF_BLO  (OFF_BHI + B_TILE_B)
#define GSM_TOTAL (OFF_BLO + B_TILE_B)   // 73728 B
#define OFF_C    OFF_T
#define LDC      132

__device__ __forceinline__ uint32_t pack_hi(float a, float b) {
    __nv_bfloat16 ha = __float2bfloat16(a), hb = __float2bfloat16(b);
    return ((uint32_t)__bfloat16_as_ushort(hb) << 16) | __bfloat16_as_ushort(ha);
}
__device__ __forceinline__ uint32_t pack_lo(float a, float b) {
    __nv_bfloat16 ha = __float2bfloat16(a), hb = __float2bfloat16(b);
    float ra = a - __bfloat162float(ha), rb = b - __bfloat162float(hb);
    __nv_bfloat16 la = __float2bfloat16(ra), lb = __float2bfloat16(rb);
    return ((uint32_t)__bfloat16_as_ushort(lb) << 16) | __bfloat16_as_ushort(la);
}

// A chunk: 128 rows x 64 k
__device__ __forceinline__ void fill_A(char* smem, const float* __restrict__ src,
                                       size_t rstride, int kofs, int tid) {
    #pragma unroll
    for (int i = 0; i < 8; i++) {
        int f = tid + 256*i;
        int row = f >> 4, c4 = (f & 15) * 4;
        float4 vv = *(const float4*)(src + (size_t)row*rstride + kofs + c4);
        uint2 hv, lv;
        hv.x = pack_hi(vv.x, vv.y); hv.y = pack_hi(vv.z, vv.w);
        lv.x = pack_lo(vv.x, vv.y); lv.y = pack_lo(vv.z, vv.w);
        uint32_t boff = (uint32_t)row*(LDA*2) + (uint32_t)c4*2;
        *(uint2*)(smem + OFF_AHI + boff) = hv;
        *(uint2*)(smem + OFF_ALO + boff) = lv;
    }
}
// B chunk: 64 k-rows x 128 n  (weights k-major: W[k][n])
__device__ __forceinline__ void fill_B(char* smem, const float* __restrict__ src,
                                       int kofs, int tid) {
    #pragma unroll
    for (int i = 0; i < 8; i++) {
        int f = tid + 256*i;
        int row = f >> 5, c4 = (f & 31) * 4;
        float4 vv = *(const float4*)(src + (size_t)(kofs + row)*H_ + c4);
        uint2 hv, lv;
        hv.x = pack_hi(vv.x, vv.y); hv.y = pack_hi(vv.z, vv.w);
        lv.x = pack_lo(vv.x, vv.y); lv.y = pack_lo(vv.z, vv.w);
        uint32_t boff = (uint32_t)row*(LDB*2) + (uint32_t)c4*2;
        *(uint2*)(smem + OFF_BHI + boff) = hv;
        *(uint2*)(smem + OFF_BLO + boff) = lv;
    }
}

// MODE 0: out = D (QKV via blockIdx.z; biases folded into attn)
// MODE 1: out = GELU(LN(D+bias)*g+b)
// MODE 2: out[m,v] = (D + bias) . oW + oB
template <int MODE>
__global__ __launch_bounds__(256, 2)
void vgemm_wmma(const float* __restrict__ A, const float* __restrict__ W,
                const float* __restrict__ b0, const float* __restrict__ W1,
                const float* __restrict__ W2,
                const float* __restrict__ lng, const float* __restrict__ lnb,
                const float* __restrict__ oW, const float* __restrict__ oB,
                float* __restrict__ out, int w_vs, int b_vs) {
    extern __shared__ char smem[];
    int tid = threadIdx.x;
    int v = blockIdx.y, m0 = blockIdx.x * 128;

    if (MODE == 0) {
        int zi = blockIdx.z;
        if (zi == 1) W = W1;
        else if (zi == 2) W = W2;
        out += (size_t)zi * M_ * V_ * H_;
    }

    float* sBias = (float*)(smem + OFF_P0);
    float* sG    = (float*)(smem + OFF_P1);
    float* sBeta = (float*)(smem + OFF_P2);
    if (MODE != 0 && tid < 128) {
        sBias[tid] = b0[(size_t)v*b_vs + tid];
        if (MODE == 1) {
            sG[tid]    = lng[(size_t)v*b_vs + tid];
            sBeta[tid] = lnb[(size_t)v*b_vs + tid];
        } else {
            sG[tid] = oW[(size_t)v*H_ + tid];
        }
    }

    int w = tid >> 5;
    int wm = w & 3;        // 4 warps over M (32 rows)
    int wn = w >> 2;       // 2 warps over N (64 cols)

    wmma::fragment<wmma::accumulator, 16, 16, 16, float> acc[2][4];
    #pragma unroll
    for (int mi = 0; mi < 2; mi++)
        #pragma unroll
        for (int ni = 0; ni < 4; ni++) wmma::fill_fragment(acc[mi][ni], 0.f);

    const __nv_bfloat16* aHi = (const __nv_bfloat16*)(smem + OFF_AHI);
    const __nv_bfloat16* aLo = (const __nv_bfloat16*)(smem + OFF_ALO);
    const __nv_bfloat16* bHi = (const __nv_bfloat16*)(smem + OFF_BHI);
    const __nv_bfloat16* bLo = (const __nv_bfloat16*)(smem + OFF_BLO);

    const float* Asrc = A + ((size_t)m0*V_ + v)*H_;
    const float* Wsrc = W + (size_t)v*w_vs;

    #pragma unroll
    for (int ch = 0; ch < 2; ch++) {
        if (ch) __syncthreads();
        fill_A(smem, Asrc, (size_t)V_*H_, ch*64, tid);
        fill_B(smem, Wsrc, ch*64, tid);
        __syncthreads();
        #pragma unroll
        for (int p = 0; p < 3; p++) {
            const __nv_bfloat16* aS = (p == 2) ? aLo : aHi;
            const __nv_bfloat16* bS = (p == 1) ? bLo : bHi;
            #pragma unroll
            for (int k0 = 0; k0 < 4; k0++) {
                int k = k0 * 16;
                wmma::fragment<wmma::matrix_a, 16, 16, 16, __nv_bfloat16, wmma::row_major> af[2];
                wmma::fragment<wmma::matrix_b, 16, 16, 16, __nv_bfloat16, wmma::row_major> bf[4];
                #pragma unroll
                for (int mi = 0; mi < 2; mi++)
                    wmma::load_matrix_sync(af[mi], aS + (size_t)(wm*32 + mi*16)*LDA + k, LDA);
                #pragma unroll
                for (int ni = 0; ni < 4; ni++)
                    wmma::load_matrix_sync(bf[ni], bS + (size_t)k*LDB + wn*64 + ni*16, LDB);
                #pragma unroll
                for (int mi = 0; mi < 2; mi++)
                    #pragma unroll
                    for (int ni = 0; ni < 4; ni++)
                        wmma::mma_sync(acc[mi][ni], af[mi], bf[ni], acc[mi][ni]);
            }
        }
    }

    __syncthreads();
    float* Cs = (float*)(smem + OFF_C);
    #pragma unroll
    for (int mi = 0; mi < 2; mi++)
        #pragma unroll
        for (int ni = 0; ni < 4; ni++)
            wmma::store_matrix_sync(Cs + (size_t)(wm*32 + mi*16)*LDC + wn*64 + ni*16,
                                    acc[mi][ni], LDC, wmma::mem_row_major);
    __syncthreads();

    int r2 = tid >> 1, half = tid & 1;
    const float* crow = Cs + (size_t)r2*LDC + half*64;
    int grow = m0 + r2;

    if constexpr (MODE == 0) {
        // coalesced copy smem -> gmem (fixes R6's uncoalesced fragment store)
        float* orow = out + ((size_t)grow*V_ + v)*H_ + half*64;
        #pragma unroll
        for (int c = 0; c < 64; c += 4)
            *(float4*)(orow + c) = *(const float4*)(crow + c);
    } else if constexpr (MODE == 1) {
        const float* bcol = sBias + half*64;
        float s = 0.f, q = 0.f;
        #pragma unroll
        for (int c = 0; c < 64; c += 4) {
            float4 cc = *(const float4*)(crow + c);
            float4 bb = *(const float4*)(bcol + c);
            float y0 = cc.x+bb.x, y1 = cc.y+bb.y, y2 = cc.z+bb.z, y3 = cc.w+bb.w;
            s += y0 + y1 + y2 + y3;
            q += y0*y0 + y1*y1 + y2*y2 + y3*y3;
        }
        s += __shfl_xor_sync(0xFFFFFFFFu, s, 1);
        q += __shfl_xor_sync(0xFFFFFFFFu, q, 1);
        float mean = s * (1.f/128.f);
        float var  = q * (1.f/128.f) - mean*mean;
        float rstd = rsqrtf(var + 1e-5f);
        float* orow = out + ((size_t)grow*V_ + v)*H_ + half*64;
        const float* gcol = sG + half*64;
        const float* lcol = sBeta + half*64;
        #pragma unroll
        for (int c = 0; c < 64; c += 4) {
            float4 cc = *(const float4*)(crow + c);
            float4 bb = *(const float4*)(bcol + c);
            float4 gg = *(const float4*)(gcol + c);
            float4 ll = *(const float4*)(lcol + c);
            float yv[4] = {cc.x+bb.x, cc.y+bb.y, cc.z+bb.z, cc.w+bb.w};
            float gv[4] = {gg.x, gg.y, gg.z, gg.w};
            float lv[4] = {ll.x, ll.y, ll.z, ll.w};
            float o4[4];
            #pragma unroll
            for (int j = 0; j < 4; j++) {
                float t2 = (yv[j] - mean) * rstd * gv[j] + lv[j];
                o4[j] = 0.5f * t2 * (1.f + erff(t2 * 0.7071067811865476f));
            }
            *(float4*)(orow + c) = make_float4(o4[0], o4[1], o4[2], o4[3]);
        }
    } else {
        const float* bcol = sBias + half*64;
        const float* gcol = sG + half*64;
        float p = 0.f;
        #pragma unroll
        for (int c = 0; c < 64; c += 4) {
            float4 cc = *(const float4*)(crow + c);
            float4 bb = *(const float4*)(bcol + c);
            float4 gg = *(const float4*)(gcol + c);
            p += (cc.x+bb.x)*gg.x + (cc.y+bb.y)*gg.y + (cc.z+bb.z)*gg.z + (cc.w+bb.w)*gg.w;
        }
        p += __shfl_xor_sync(0xFFFFFFFFu, p, 1);
        if (half == 0)
            out[(size_t)grow*V_ + v] = p + oB[v];
    }
}

// ================= flash-style mma attention ===============================
// One block per (b, v, head). 256 threads = 8 warps; warp owns 32 queries.
// K packed bf16 hi/lo [key][dh-pairs] stride 12 u32 (conflict-free B loads).
// V transposed bf16 hi/lo [dh][key-pairs] stride 132 u32.
#define KSTR 12
#define VSTR 132

__global__ __launch_bounds__(256)
void attn_mma(const float* __restrict__ qkv,
              const float* __restrict__ bq, const float* __restrict__ bk,
              const float* __restrict__ bv, float* __restrict__ out) {
    __shared__ uint32_t khi[256*KSTR], klo[256*KSTR];
    __shared__ uint32_t vthi[16*VSTR], vtlo[16*VSTR];

    int bid = blockIdx.x;
    int n = bid & 7, v = (bid >> 3) & 63, b = bid >> 9;
    int tid = threadIdx.x, w = tid >> 5, lane = tid & 31;

    const float* q  = qkv;
    const float* kk = qkv + (size_t)M_*V_*H_;
    const float* vv = qkv + 2*(size_t)M_*V_*H_;
    size_t rstr = (size_t)V_*H_;
    size_t base = ((size_t)(b*S_)*V_ + v)*H_ + n*DH_;
    size_t bofs = (size_t)v*H_ + n*DH_;

    // ---- stage K (packed hi/lo) and V (transposed hi/lo); key = tid ----
    {
        int key = tid;
        const float4* kp = (const float4*)(kk + base + (size_t)key*rstr);
        const float4* vp = (const float4*)(vv + base + (size_t)key*rstr);
        float kr[16], vr[16];
        #pragma unroll
        for (int i = 0; i < 4; i++) {
            float4 a = kp[i], c = vp[i];
            float4 bb = *(const float4*)(bk + bofs + i*4);
            float4 cb = *(const float4*)(bv + bofs + i*4);
            kr[i*4+0]=a.x+bb.x; kr[i*4+1]=a.y+bb.y; kr[i*4+2]=a.z+bb.z; kr[i*4+3]=a.w+bb.w;
            vr[i*4+0]=c.x+cb.x; vr[i*4+1]=c.y+cb.y; vr[i*4+2]=c.z+cb.z; vr[i*4+3]=c.w+cb.w;
        }
        #pragma unroll
        for (int d = 0; d < 8; d++) {
            uint32_t h = pkrn(kr[2*d], kr[2*d+1]);
            khi[key*KSTR + d] = h;
            klo[key*KSTR + d] = pklo(kr[2*d], kr[2*d+1], h);
        }
        unsigned short* vthi16 = (unsigned short*)vthi;
        unsigned short* vtlo16 = (unsigned short*)vtlo;
        #pragma unroll
        for (int c = 0; c < 16; c++) {
            __nv_bfloat16 hb = __float2bfloat16(vr[c]);
            float lo = vr[c] - __bfloat162float(hb);
            __nv_bfloat16 lb = __float2bfloat16(lo);
            vthi16[c*(2*VSTR) + key] = __bfloat16_as_ushort(hb);
            vtlo16[c*(2*VSTR) + key] = __bfloat16_as_ushort(lb);
        }
    }

    // ---- load Q fragments (pre-scaled by 1/sqrt(DH) = 0.25) ----
    int rq = w*32 + (lane >> 2);
    int c2 = (lane & 3) * 2;
    float2 bq0 = make_float2(bq[bofs + c2],     bq[bofs + c2 + 1]);
    float2 bq1 = make_float2(bq[bofs + c2 + 8], bq[bofs + c2 + 9]);
    uint32_t qhi[2][4], qlo[2][4];
    #pragma unroll
    for (int mi = 0; mi < 2; mi++) {
        int rA = rq + mi*16, rB = rA + 8;
        float2 x00 = *(const float2*)(q + base + (size_t)rA*rstr + c2);
        float2 x01 = *(const float2*)(q + base + (size_t)rA*rstr + c2 + 8);
        float2 x10 = *(const float2*)(q + base + (size_t)rB*rstr + c2);
        float2 x11 = *(const float2*)(q + base + (size_t)rB*rstr + c2 + 8);
        x00.x = (x00.x + bq0.x)*0.25f; x00.y = (x00.y + bq0.y)*0.25f;
        x01.x = (x01.x + bq1.x)*0.25f; x01.y = (x01.y + bq1.y)*0.25f;
        x10.x = (x10.x + bq0.x)*0.25f; x10.y = (x10.y + bq0.y)*0.25f;
        x11.x = (x11.x + bq1.x)*0.25f; x11.y = (x11.y + bq1.y)*0.25f;
        qhi[mi][0] = pkrn(x00.x, x00.y); qlo[mi][0] = pklo(x00.x, x00.y, qhi[mi][0]);
        qhi[mi][1] = pkrn(x10.x, x10.y); qlo[mi][1] = pklo(x10.x, x10.y, qhi[mi][1]);
        qhi[mi][2] = pkrn(x01.x, x01.y); qlo[mi][2] = pklo(x01.x, x01.y, qhi[mi][2]);
        qhi[mi][3] = pkrn(x11.x, x11.y); qlo[mi][3] = pklo(x11.x, x11.y, qhi[mi][3]);
    }
    __syncthreads();

    float oacc[2][2][4];
    #pragma unroll
    for (int mi = 0; mi < 2; mi++)
        #pragma unroll
        for (int d = 0; d < 2; d++)
            #pragma unroll
            for (int e = 0; e < 4; e++) oacc[mi][d][e] = 0.f;
    float mrun[2][2] = {{-1e30f,-1e30f},{-1e30f,-1e30f}};
    float lrun[2][2] = {{0.f,0.f},{0.f,0.f}};

    #pragma unroll
    for (int kt = 0; kt < 4; kt++) {
        int kb = kt * 64;
        uint32_t sbh[8][2], sbl[8][2];
        #pragma unroll
        for (int j = 0; j < 8; j++) {
            int key = kb + j*8 + (lane >> 2);
            int ci  = lane & 3;
            sbh[j][0] = khi[key*KSTR + ci];     sbh[j][1] = khi[key*KSTR + ci + 4];
            sbl[j][0] = klo[key*KSTR + ci];     sbl[j][1] = klo[key*KSTR + ci + 4];
        }
        #pragma unroll
        for (int mi = 0; mi < 2; mi++) {
            float C[8][4];
            #pragma unroll
            for (int j = 0; j < 8; j++) { C[j][0]=0.f; C[j][1]=0.f; C[j][2]=0.f; C[j][3]=0.f; }
            #pragma unroll
            for (int j = 0; j < 8; j++) {
                mma16816(C[j], qhi[mi], sbh[j][0], sbh[j][1]);
                mma16816(C[j], qhi[mi], sbl[j][0], sbl[j][1]);
                mma16816(C[j], qlo[mi], sbh[j][0], sbh[j][1]);
            }
            // online softmax: rows A = lane/4, B = lane/4 + 8
            float mA = -1e30f, mB = -1e30f;
            #pragma unroll
            for (int j = 0; j < 8; j++) {
                mA = fmaxf(mA, fmaxf(C[j][0], C[j][1]));
                mB = fmaxf(mB, fmaxf(C[j][2], C[j][3]));
            }
            mA = fmaxf(mA, __shfl_xor_sync(0xFFFFFFFFu, mA, 1));
            mA = fmaxf(mA, __shfl_xor_sync(0xFFFFFFFFu, mA, 2));
            mB = fmaxf(mB, __shfl_xor_sync(0xFFFFFFFFu, mB, 1));
            mB = fmaxf(mB, __shfl_xor_sync(0xFFFFFFFFu, mB, 2));
            float nA = fmaxf(mrun[mi][0], mA), nB = fmaxf(mrun[mi][1], mB);
            float cA = __expf(mrun[mi][0] - nA), cB = __expf(mrun[mi][1] - nB);
            mrun[mi][0] = nA; mrun[mi][1] = nB;
            float sA = 0.f, sB = 0.f;
            #pragma unroll
            for (int j = 0; j < 8; j++) {
                C[j][0] = __expf(C[j][0] - nA); C[j][1] = __expf(C[j][1] - nA);
                C[j][2] = __expf(C[j][2] - nB); C[j][3] = __expf(C[j][3] - nB);
                sA += C[j][0] + C[j][1];
                sB += C[j][2] + C[j][3];
            }
            sA += __shfl_xor_sync(0xFFFFFFFFu, sA, 1);
            sA += __shfl_xor_sync(0xFFFFFFFFu, sA, 2);
            sB += __shfl_xor_sync(0xFFFFFFFFu, sB, 1);
            sB += __shfl_xor_sync(0xFFFFFFFFu, sB, 2);
            lrun[mi][0] = lrun[mi][0]*cA + sA;
            lrun[mi][1] = lrun[mi][1]*cB + sB;
            #pragma unroll
            for (int d = 0; d < 2; d++) {
                oacc[mi][d][0] *= cA; oacc[mi][d][1] *= cA;
                oacc[mi][d][2] *= cB; oacc[mi][d][3] *= cB;
            }
            // PV: pack P into A-frags (C-pair -> A identity), 3-pass split
            #pragma unroll
            for (int u = 0; u < 4; u++) {
                uint32_t pa[4], pl[4];
                pa[0] = pkrn(C[2*u][0],   C[2*u][1]);   pl[0] = pklo(C[2*u][0],   C[2*u][1],   pa[0]);
                pa[1] = pkrn(C[2*u][2],   C[2*u][3]);   pl[1] = pklo(C[2*u][2],   C[2*u][3],   pa[1]);
                pa[2] = pkrn(C[2*u+1][0], C[2*u+1][1]); pl[2] = pklo(C[2*u+1][0], C[2*u+1][1], pa[2]);
                pa[3] = pkrn(C[2*u+1][2], C[2*u+1][3]); pl[3] = pklo(C[2*u+1][2], C[2*u+1][3], pa[3]);
                int kb2h = (kb + u*16) >> 1;
                #pragma unroll
                for (int d = 0; d < 2; d++) {
                    int nrow = d*8 + (lane >> 2);
                    uint32_t b0h = vthi[nrow*VSTR + kb2h + (lane & 3)];
                    uint32_t b1h = vthi[nrow*VSTR + kb2h + 4 + (lane & 3)];
                    uint32_t b0l = vtlo[nrow*VSTR + kb2h + (lane & 3)];
                    uint32_t b1l = vtlo[nrow*VSTR + kb2h + 4 + (lane & 3)];
                    mma16816(oacc[mi][d], pa, b0h, b1h);
                    mma16816(oacc[mi][d], pa, b0l, b1l);
                    mma16816(oacc[mi][d], pl, b0h, b1h);
                }
            }
        }
    }

    // ---- write normalized output (fp32) ----
    #pragma unroll
    for (int mi = 0; mi < 2; mi++) {
        float iA = 1.f / lrun[mi][0], iB = 1.f / lrun[mi][1];
        int rA = w*32 + mi*16 + (lane >> 2), rB = rA + 8;
        #pragma unroll
        for (int d = 0; d < 2; d++) {
            *(float2*)(out + base + (size_t)rA*rstr + d*8 + c2) =
                make_float2(oacc[mi][d][0]*iA, oacc[mi][d][1]*iA);
            *(float2*)(out + base + (size_t)rB*rstr + d*8 + c2) =
                make_float2(oacc[mi][d][2]*iB, oacc[mi][d][3]*iB);
        }
    }
}

// ---------------- launch ---------------------------------------------------
extern "C" void kernel_launch(void* const* d_in, const int* in_sizes, int n_in,
                              void* d_out, int out_size) {
    const float* x       = (const float*)d_in[0];
    const float* adjlog  = (const float*)d_in[1];
    const float* var_emb = (const float*)d_in[2];
    const float* temp_emb= (const float*)d_in[3];
    const float* mech_W  = (const float*)d_in[4];
    const float* mech_b  = (const float*)d_in[5];
    const float* ln_g    = (const float*)d_in[6];
    const float* ln_b    = (const float*)d_in[7];
    const float* Wq      = (const float*)d_in[8];
    const float* Wk      = (const float*)d_in[9];
    const float* Wv      = (const float*)d_in[10];
    const float* Wo      = (const float*)d_in[11];
    const float* bq      = (const float*)d_in[12];
    const float* bk      = (const float*)d_in[13];
    const float* bv      = (const float*)d_in[14];
    const float* bo      = (const float*)d_in[15];
    const float* out_W   = (const float*)d_in[16];
    const float* out_b   = (const float*)d_in[17];
    float* out = (float*)d_out;

    float *adjT, *z, *z2, *qkv;
    cudaGetSymbolAddress((void**)&adjT, g_adjT);
    cudaGetSymbolAddress((void**)&z,    g_z);
    cudaGetSymbolAddress((void**)&z2,   g_z2);
    cudaGetSymbolAddress((void**)&qkv,  g_qkv);

    cudaFuncSetAttribute(vgemm_wmma<0>, cudaFuncAttributeMaxDynamicSharedMemorySize, GSM_TOTAL);
    cudaFuncSetAttribute(vgemm_wmma<1>, cudaFuncAttributeMaxDynamicSharedMemorySize, GSM_TOTAL);
    cudaFuncSetAttribute(vgemm_wmma<2>, cudaFuncAttributeMaxDynamicSharedMemorySize, GSM_TOTAL);

    prep_adj_kernel<<<(V_*V_*LP1_ + 255)/256, 256>>>(adjlog, adjT);
    stage1_kernel<<<M_, 256>>>(x, adjT, var_emb, temp_emb, z);

    dim3 gg(M_/128, V_);
    vgemm_wmma<1><<<gg, 256, GSM_TOTAL>>>(z,  mech_W + 0*H_*H_, mech_b + 0*H_,
                                          nullptr, nullptr,
                                          ln_g + 0*H_, ln_b + 0*H_, nullptr, nullptr,
                                          z2, NL_*H_*H_, NL_*H_);
    vgemm_wmma<1><<<gg, 256, GSM_TOTAL>>>(z2, mech_W + 1*H_*H_, mech_b + 1*H_,
                                          nullptr, nullptr,
                                          ln_g + 1*H_, ln_b + 1*H_, nullptr, nullptr,
                                          z,  NL_*H_*H_, NL_*H_);
    vgemm_wmma<1><<<gg, 256, GSM_TOTAL>>>(z,  mech_W + 2*H_*H_, mech_b + 2*H_,
                                          nullptr, nullptr,
                                          ln_g + 2*H_, ln_b + 2*H_, nullptr, nullptr,
                                          z2, NL_*H_*H_, NL_*H_);
    dim3 gq(M_/128, V_, 3);
    vgemm_wmma<0><<<gq, 256, GSM_TOTAL>>>(z2, Wq, nullptr, Wk, Wv,
                                          nullptr, nullptr, nullptr, nullptr,
                                          qkv, H_*H_, H_);
    attn_mma<<<B_*V_*NH_, 256>>>(qkv, bq, bk, bv, z);
    vgemm_wmma<2><<<gg, 256, GSM_TOTAL>>>(z, Wo, bo, nullptr, nullptr,
                                          nullptr, nullptr, out_W, out_b, out, H_*H_, H_);
}

// round 9
// speedup vs baseline: 1.8352x; 1.1986x over previous
#include <cuda_runtime.h>
#include <cuda_bf16.h>
#include <mma.h>
#include <math.h>
#include <stdint.h>

using namespace nvcuda;

#define B_   4
#define S_   256
#define V_   64
#define LP1_ 11
#define H_   128
#define NH_  8
#define DH_  16
#define NL_  3
#define M_   (B_*S_)   // 1024

// ---------------- scratch (device globals; no allocation) ----------------
__device__ float g_adjT[V_*LP1_*V_];
__device__ float g_z [M_*V_*H_];
__device__ float g_z2[M_*V_*H_];
__device__ float g_qkv[3*M_*V_*H_];
__device__ __align__(16) __nv_bfloat16 g_whi[7*V_*H_*H_];
__device__ __align__(16) __nv_bfloat16 g_wlo[7*V_*H_*H_];

// ---------------- pack helpers --------------------------------------------
__device__ __forceinline__ uint32_t pkrn(float x, float y) {
    __nv_bfloat162 h = __floats2bfloat162_rn(x, y);
    return *(uint32_t*)&h;
}
__device__ __forceinline__ uint32_t pklo(float x, float y, uint32_t hi) {
    __nv_bfloat162 h = *(__nv_bfloat162*)&hi;
    return pkrn(x - __bfloat162float(h.x), y - __bfloat162float(h.y));
}
// truncation split: hi = top16(f) exactly, lo = trunc16(f - hi)
__device__ __forceinline__ void pack_trunc2(float a, float b, uint32_t& h, uint32_t& l) {
    uint32_t ba = __float_as_uint(a), bb = __float_as_uint(b);
    h = __byte_perm(ba, bb, 0x7632);
    float ra = a - __uint_as_float(ba & 0xFFFF0000u);
    float rb = b - __uint_as_float(bb & 0xFFFF0000u);
    l = __byte_perm(__float_as_uint(ra), __float_as_uint(rb), 0x7632);
}

__device__ __forceinline__ uint32_t smem_u32(const void* p) {
    uint32_t a;
    asm("{ .reg .u64 t; cvta.to.shared.u64 t, %1; cvt.u32.u64 %0, t; }" : "=r"(a) : "l"(p));
    return a;
}
__device__ __forceinline__ void cpa16(uint32_t dst, const void* src) {
    asm volatile("cp.async.ca.shared.global [%0], [%1], 16;" :: "r"(dst), "l"(src));
}
#define CP_COMMIT() asm volatile("cp.async.commit_group;" ::: "memory")
#define CP_WAIT(n)  asm volatile("cp.async.wait_group %0;" :: "n"(n) : "memory")

// mma.sync m16n8k16 row.col bf16 -> f32 accumulate in place (attention)
__device__ __forceinline__ void mma16816(float* c, const uint32_t* a, uint32_t b0, uint32_t b1) {
    asm volatile(
        "mma.sync.aligned.m16n8k16.row.col.f32.bf16.bf16.f32 "
        "{%0,%1,%2,%3}, {%4,%5,%6,%7}, {%8,%9}, {%0,%1,%2,%3};\n"
        : "+f"(c[0]), "+f"(c[1]), "+f"(c[2]), "+f"(c[3])
        : "r"(a[0]), "r"(a[1]), "r"(a[2]), "r"(a[3]), "r"(b0), "r"(b1));
}

// ---------------- stage 0: sigmoid + transpose of adjacency --------------
__global__ void prep_adj_kernel(const float* __restrict__ logits, float* __restrict__ adjT) {
    int idx = blockIdx.x * 256 + threadIdx.x;
    if (idx >= V_*V_*LP1_) return;
    int s = idx % V_;
    int r = idx / V_;
    int l = r % LP1_;
    int i = r / LP1_;
    float x = logits[(s*V_ + i)*LP1_ + l];
    adjT[idx] = 1.f / (1.f + __expf(-x));
}

// ---------------- weight split (k-major, rounding split) ------------------
__global__ void prep_w_kernel(const float* __restrict__ mW,
                              const float* __restrict__ Wq, const float* __restrict__ Wk,
                              const float* __restrict__ Wv, const float* __restrict__ Wo,
                              __nv_bfloat16* __restrict__ whi, __nv_bfloat16* __restrict__ wlo) {
    int idx = blockIdx.x * 256 + threadIdx.x;      // one float4
    const int per_mat = H_*H_/4;
    if (idx >= 7*V_*per_mat) return;
    int slotmat = idx / per_mat;
    int within  = idx - slotmat * per_mat;
    int s = slotmat >> 6, v = slotmat & 63;
    const float* src;
    if (s < 3)       src = mW + ((size_t)(v*NL_ + s))*H_*H_;
    else if (s == 3) src = Wq + (size_t)v*H_*H_;
    else if (s == 4) src = Wk + (size_t)v*H_*H_;
    else if (s == 5) src = Wv + (size_t)v*H_*H_;
    else             src = Wo + (size_t)v*H_*H_;
    float4 f = *(const float4*)(src + within*4);
    uint32_t h0 = pkrn(f.x, f.y), h1 = pkrn(f.z, f.w);
    uint32_t l0 = pklo(f.x, f.y, h0), l1 = pklo(f.z, f.w, h1);
    size_t o = (size_t)slotmat*H_*H_ + within*4;
    *(uint2*)(whi + o) = make_uint2(h0, h1);
    *(uint2*)(wlo + o) = make_uint2(l0, l1);
}

// ---------------- stage 1: z[b,t,i,h] -------------------------------------
__global__ __launch_bounds__(256)
void stage1_kernel(const float* __restrict__ x, const float* __restrict__ adjT,
                   const float* __restrict__ var_emb, const float* __restrict__ temp_emb,
                   float* __restrict__ z) {
    int bt = blockIdx.x;
    int b = bt >> 8;
    int t = bt & 255;
    __shared__ float xw[LP1_][V_];
    __shared__ float Am[V_][V_ + 1];
    __shared__ float Bls[V_][LP1_ + 1];
    int tid = threadIdx.x;

    for (int p = tid; p < LP1_*V_; p += 256) {
        int l = p / V_, s = p % V_;
        int tt = t - l;
        xw[l][s] = (tt >= 0) ? x[((size_t)(b*S_ + tt))*V_ + s] : 0.f;
    }
    __syncthreads();

    for (int p = tid; p < V_*V_; p += 256) {
        int i = p >> 6, s = p & 63;
        const float* ap = adjT + (size_t)i*LP1_*V_ + s;
        float a = 0.f;
        #pragma unroll
        for (int l = 0; l < LP1_; l++) a += xw[l][s] * ap[l*V_];
        Am[i][s] = a;
    }
    for (int p = tid; p < V_*LP1_; p += 256) {
        int i = p / LP1_, l = p % LP1_;
        const float* ap = adjT + ((size_t)i*LP1_ + l)*V_;
        float a = 0.f;
        #pragma unroll 8
        for (int s = 0; s < V_; s++) a += xw[l][s] * ap[s];
        Bls[i][l] = a;
    }
    __syncthreads();

    int tx = tid & 15, ty = tid >> 4;
    float acc[4][8];
    #pragma unroll
    for (int r = 0; r < 4; r++)
        #pragma unroll
        for (int c = 0; c < 8; c++) acc[r][c] = 0.f;

    for (int s = 0; s < V_; s++) {
        float a0 = Am[ty*4+0][s], a1 = Am[ty*4+1][s], a2 = Am[ty*4+2][s], a3 = Am[ty*4+3][s];
        const float4* vp = (const float4*)(var_emb + (size_t)s*H_ + tx*8);
        float4 v0 = vp[0], v1 = vp[1];
        float bv[8] = {v0.x,v0.y,v0.z,v0.w,v1.x,v1.y,v1.z,v1.w};
        #pragma unroll
        for (int c = 0; c < 8; c++) {
            acc[0][c] += a0*bv[c]; acc[1][c] += a1*bv[c];
            acc[2][c] += a2*bv[c]; acc[3][c] += a3*bv[c];
        }
    }
    #pragma unroll
    for (int l = 0; l < LP1_; l++) {
        float a0 = Bls[ty*4+0][l], a1 = Bls[ty*4+1][l], a2 = Bls[ty*4+2][l], a3 = Bls[ty*4+3][l];
        const float4* vp = (const float4*)(temp_emb + (size_t)l*H_ + tx*8);
        float4 v0 = vp[0], v1 = vp[1];
        float bv[8] = {v0.x,v0.y,v0.z,v0.w,v1.x,v1.y,v1.z,v1.w};
        #pragma unroll
        for (int c = 0; c < 8; c++) {
            acc[0][c] += a0*bv[c]; acc[1][c] += a1*bv[c];
            acc[2][c] += a2*bv[c]; acc[3][c] += a3*bv[c];
        }
    }
    #pragma unroll
    for (int r = 0; r < 4; r++) {
        int i = ty*4 + r;
        float* zp = z + ((size_t)bt*V_ + i)*H_ + tx*8;
        *(float4*)(zp)   = make_float4(acc[r][0], acc[r][1], acc[r][2], acc[r][3]);
        *(float4*)(zp+4) = make_float4(acc[r][4], acc[r][5], acc[r][6], acc[r][7]);
    }
}

// ========= fused GEMM machinery: BM=64, full K in A smem, W double-buffer ==
#define FP_PAR   0
#define FSA_HI   4608
#define FSA_LO   (FSA_HI + 17408)
#define FSB0_HI  (FSA_LO + 17408)
#define FSB0_LO  (FSB0_HI + 17408)
#define FSB1_HI  (FSB0_LO + 17408)
#define FSB1_LO  (FSB1_HI + 17408)
#define FGSM     (FSB1_LO + 17408)    // 109056 B
#define FOFF_C   FSB0_HI
#define FLDC     132
#define LD2      136   // bf16 elems per smem tile row

// A tile fill: 64 rows x 128 cols fp32 -> bf16 hi/lo smem (truncation split)
__device__ __forceinline__ void fillA(char* smem, const float* __restrict__ src,
                                      size_t rstr, int tid) {
    __nv_bfloat16* aH = (__nv_bfloat16*)(smem + FSA_HI);
    __nv_bfloat16* aL = (__nv_bfloat16*)(smem + FSA_LO);
    #pragma unroll
    for (int i = 0; i < 8; i++) {
        int f = tid + 256*i;
        int row = f >> 5, c4 = f & 31;
        float4 vv = *(const float4*)(src + (size_t)row*rstr + c4*4);
        uint32_t h0, l0, h1, l1;
        pack_trunc2(vv.x, vv.y, h0, l0);
        pack_trunc2(vv.z, vv.w, h1, l1);
        int off = row*LD2 + c4*4;
        *(uint2*)(aH + off) = make_uint2(h0, h1);
        *(uint2*)(aL + off) = make_uint2(l0, l1);
    }
}

// cp.async one 64-row W chunk (hi+lo) into SB buffer
__device__ __forceinline__ void cpW(uint32_t sb_hi, uint32_t sb_lo,
                                    const __nv_bfloat16* __restrict__ hi,
                                    const __nv_bfloat16* __restrict__ lo,
                                    int rowbase, int tid) {
    #pragma unroll
    for (int i = 0; i < 4; i++) {
        int f = tid + 256*i;
        int row = f >> 4, seg = f & 15;
        uint32_t so = (uint32_t)row*(LD2*2) + seg*16;
        size_t go = (size_t)(rowbase + row)*H_ + seg*8;
        cpa16(sb_hi + so, hi + go);
        cpa16(sb_lo + so, lo + go);
    }
}

// one K-chunk of mma: warp tile 32x32 (wm over 2 M halves, wn over 4 N quarters)
__device__ __forceinline__ void mma_chunk(char* smem, int sbHi, int sbLo, int ck,
    int wm, int wn, wmma::fragment<wmma::accumulator,16,16,16,float> (&acc)[2][2]) {
    const __nv_bfloat16* aH = (const __nv_bfloat16*)(smem + FSA_HI);
    const __nv_bfloat16* aL = (const __nv_bfloat16*)(smem + FSA_LO);
    const __nv_bfloat16* bH = (const __nv_bfloat16*)(smem + sbHi);
    const __nv_bfloat16* bL = (const __nv_bfloat16*)(smem + sbLo);
    #pragma unroll
    for (int k0 = 0; k0 < 4; k0++) {
        int ka = ck*64 + k0*16;
        wmma::fragment<wmma::matrix_a, 16, 16, 16, __nv_bfloat16, wmma::row_major> afH[2], afL[2];
        wmma::fragment<wmma::matrix_b, 16, 16, 16, __nv_bfloat16, wmma::row_major> bfH[2], bfL[2];
        #pragma unroll
        for (int mi = 0; mi < 2; mi++) {
            wmma::load_matrix_sync(afH[mi], aH + (size_t)(wm*32 + mi*16)*LD2 + ka, LD2);
            wmma::load_matrix_sync(afL[mi], aL + (size_t)(wm*32 + mi*16)*LD2 + ka, LD2);
        }
        #pragma unroll
        for (int ni = 0; ni < 2; ni++) {
            wmma::load_matrix_sync(bfH[ni], bH + (size_t)(k0*16)*LD2 + wn*32 + ni*16, LD2);
            wmma::load_matrix_sync(bfL[ni], bL + (size_t)(k0*16)*LD2 + wn*32 + ni*16, LD2);
        }
        #pragma unroll
        for (int mi = 0; mi < 2; mi++)
            #pragma unroll
            for (int ni = 0; ni < 2; ni++) {
                wmma::mma_sync(acc[mi][ni], afH[mi], bfH[ni], acc[mi][ni]);
                wmma::mma_sync(acc[mi][ni], afH[mi], bfL[ni], acc[mi][ni]);
                wmma::mma_sync(acc[mi][ni], afL[mi], bfH[ni], acc[mi][ni]);
            }
    }
}

// run one layer: cp.async double-buffered W chunks + mma; leaves acc filled.
__device__ __forceinline__ void run_layer(char* smem, uint32_t sbase,
    const __nv_bfloat16* whi, const __nv_bfloat16* wlo, int wm, int wn, int tid,
    wmma::fragment<wmma::accumulator,16,16,16,float> (&acc)[2][2]) {
    #pragma unroll
    for (int mi = 0; mi < 2; mi++)
        #pragma unroll
        for (int ni = 0; ni < 2; ni++) wmma::fill_fragment(acc[mi][ni], 0.f);
    cpW(sbase + FSB0_HI, sbase + FSB0_LO, whi, wlo, 0,  tid);
    CP_COMMIT();
    cpW(sbase + FSB1_HI, sbase + FSB1_LO, whi, wlo, 64, tid);
    CP_COMMIT();
    CP_WAIT(1);
    __syncthreads();
    mma_chunk(smem, FSB0_HI, FSB0_LO, 0, wm, wn, acc);
    CP_WAIT(0);
    __syncthreads();
    mma_chunk(smem, FSB1_HI, FSB1_LO, 1, wm, wn, acc);
    __syncthreads();   // all mma done; C region (over SB0) free
    float* Cs = (float*)(smem + FOFF_C);
    #pragma unroll
    for (int mi = 0; mi < 2; mi++)
        #pragma unroll
        for (int ni = 0; ni < 2; ni++)
            wmma::store_matrix_sync(Cs + (size_t)(wm*32 + mi*16)*FLDC + wn*32 + ni*16,
                                    acc[mi][ni], FLDC, wmma::mem_row_major);
    __syncthreads();
}

// ---------------- fused 3-layer mech chain ---------------------------------
__global__ __launch_bounds__(256, 2)
void fused_mech(const float* __restrict__ z, const float* __restrict__ mech_b,
                const float* __restrict__ lng, const float* __restrict__ lnb,
                const __nv_bfloat16* __restrict__ whi, const __nv_bfloat16* __restrict__ wlo,
                float* __restrict__ outz) {
    extern __shared__ char smem[];
    uint32_t sbase = smem_u32(smem);
    int tid = threadIdx.x;
    int v = blockIdx.y, m0 = blockIdx.x * 64;
    int w = tid >> 5, wm = w & 1, wn = w >> 1;

    float* sBias = (float*)(smem + FP_PAR);
    float* sG    = sBias + 3*128;
    float* sBeta = sG + 3*128;
    if (tid < 128) {
        #pragma unroll
        for (int li = 0; li < 3; li++) {
            sBias[li*128 + tid] = mech_b[(size_t)v*NL_*H_ + li*H_ + tid];
            sG[li*128 + tid]    = lng  [(size_t)v*NL_*H_ + li*H_ + tid];
            sBeta[li*128 + tid] = lnb  [(size_t)v*NL_*H_ + li*H_ + tid];
        }
    }
    fillA(smem, z + ((size_t)m0*V_ + v)*H_, (size_t)V_*H_, tid);
    __syncthreads();

    wmma::fragment<wmma::accumulator,16,16,16,float> acc[2][2];
    int row = tid >> 2, qt = tid & 3;
    float* Cs = (float*)(smem + FOFF_C);
    __nv_bfloat16* aH = (__nv_bfloat16*)(smem + FSA_HI);
    __nv_bfloat16* aL = (__nv_bfloat16*)(smem + FSA_LO);

    #pragma unroll
    for (int li = 0; li < 3; li++) {
        const __nv_bfloat16* wh = whi + ((size_t)li*V_ + v)*H_*H_;
        const __nv_bfloat16* wl = wlo + ((size_t)li*V_ + v)*H_*H_;
        run_layer(smem, sbase, wh, wl, wm, wn, tid, acc);

        // epilogue: quarter-row per thread, LN + GELU
        const float* crow = Cs + (size_t)row*FLDC + qt*32;
        const float* bcol = sBias + li*128 + qt*32;
        float s = 0.f, q = 0.f;
        #pragma unroll
        for (int c = 0; c < 32; c += 4) {
            float4 cc = *(const float4*)(crow + c);
            float4 bb = *(const float4*)(bcol + c);
            float y0 = cc.x+bb.x, y1 = cc.y+bb.y, y2 = cc.z+bb.z, y3 = cc.w+bb.w;
            s += y0 + y1 + y2 + y3;
            q += y0*y0 + y1*y1 + y2*y2 + y3*y3;
        }
        s += __shfl_xor_sync(0xFFFFFFFFu, s, 1);
        q += __shfl_xor_sync(0xFFFFFFFFu, q, 1);
        s += __shfl_xor_sync(0xFFFFFFFFu, s, 2);
        q += __shfl_xor_sync(0xFFFFFFFFu, q, 2);
        float mean = s * (1.f/128.f);
        float var  = q * (1.f/128.f) - mean*mean;
        float rstd = rsqrtf(var + 1e-5f);
        const float* gcol = sG + li*128 + qt*32;
        const float* lcol = sBeta + li*128 + qt*32;
        #pragma unroll
        for (int c = 0; c < 32; c += 4) {
            float4 cc = *(const float4*)(crow + c);
            float4 bb = *(const float4*)(bcol + c);
            float4 gg = *(const float4*)(gcol + c);
            float4 ll = *(const float4*)(lcol + c);
            float yv[4] = {cc.x+bb.x, cc.y+bb.y, cc.z+bb.z, cc.w+bb.w};
            float gv[4] = {gg.x, gg.y, gg.z, gg.w};
            float lv[4] = {ll.x, ll.y, ll.z, ll.w};
            float o4[4];
            #pragma unroll
            for (int j = 0; j < 4; j++) {
                float t2 = (yv[j] - mean) * rstd * gv[j] + lv[j];
                o4[j] = 0.5f * t2 * (1.f + erff(t2 * 0.7071067811865476f));
            }
            if (li < 2) {
                uint32_t h0, l0, h1, l1;
                pack_trunc2(o4[0], o4[1], h0, l0);
                pack_trunc2(o4[2], o4[3], h1, l1);
                int off = row*LD2 + qt*32 + c;
                *(uint2*)(aH + off) = make_uint2(h0, h1);
                *(uint2*)(aL + off) = make_uint2(l0, l1);
            } else {
                *(float4*)(outz + ((size_t)(m0+row)*V_ + v)*H_ + qt*32 + c) =
                    make_float4(o4[0], o4[1], o4[2], o4[3]);
            }
        }
        __syncthreads();   // A updated / C consumed before next layer reuses SB0
    }
}

// ---------------- fused QKV (A converted once; 3 weight slots) -------------
__global__ __launch_bounds__(256, 2)
void fused_qkv(const float* __restrict__ z2,
               const __nv_bfloat16* __restrict__ whi, const __nv_bfloat16* __restrict__ wlo,
               float* __restrict__ qkv) {
    extern __shared__ char smem[];
    uint32_t sbase = smem_u32(smem);
    int tid = threadIdx.x;
    int v = blockIdx.y, m0 = blockIdx.x * 64;
    int w = tid >> 5, wm = w & 1, wn = w >> 1;

    fillA(smem, z2 + ((size_t)m0*V_ + v)*H_, (size_t)V_*H_, tid);
    __syncthreads();

    wmma::fragment<wmma::accumulator,16,16,16,float> acc[2][2];
    int row = tid >> 2, qt = tid & 3;
    float* Cs = (float*)(smem + FOFF_C);

    #pragma unroll
    for (int zi = 0; zi < 3; zi++) {
        const __nv_bfloat16* wh = whi + ((size_t)(3+zi)*V_ + v)*H_*H_;
        const __nv_bfloat16* wl = wlo + ((size_t)(3+zi)*V_ + v)*H_*H_;
        run_layer(smem, sbase, wh, wl, wm, wn, tid, acc);
        float* orow = qkv + (size_t)zi*M_*V_*H_ + ((size_t)(m0+row)*V_ + v)*H_ + qt*32;
        const float* crow = Cs + (size_t)row*FLDC + qt*32;
        #pragma unroll
        for (int c = 0; c < 32; c += 4)
            *(float4*)(orow + c) = *(const float4*)(crow + c);
        __syncthreads();
    }
}

// ---------------- O-proj + output head -------------------------------------
__global__ __launch_bounds__(256, 2)
void oproj_gemm(const float* __restrict__ att,
                const __nv_bfloat16* __restrict__ whi, const __nv_bfloat16* __restrict__ wlo,
                const float* __restrict__ bo, const float* __restrict__ oW,
                const float* __restrict__ oB, float* __restrict__ out) {
    extern __shared__ char smem[];
    uint32_t sbase = smem_u32(smem);
    int tid = threadIdx.x;
    int v = blockIdx.y, m0 = blockIdx.x * 64;
    int w = tid >> 5, wm = w & 1, wn = w >> 1;

    float* sBias = (float*)(smem + FP_PAR);
    float* sG    = sBias + 3*128;
    if (tid < 128) {
        sBias[tid] = bo[(size_t)v*H_ + tid];
        sG[tid]    = oW[(size_t)v*H_ + tid];
    }
    fillA(smem, att + ((size_t)m0*V_ + v)*H_, (size_t)V_*H_, tid);
    __syncthreads();

    wmma::fragment<wmma::accumulator,16,16,16,float> acc[2][2];
    const __nv_bfloat16* wh = whi + ((size_t)6*V_ + v)*H_*H_;
    const __nv_bfloat16* wl = wlo + ((size_t)6*V_ + v)*H_*H_;
    run_layer(smem, sbase, wh, wl, wm, wn, tid, acc);

    int row = tid >> 2, qt = tid & 3;
    float* Cs = (float*)(smem + FOFF_C);
    const float* crow = Cs + (size_t)row*FLDC + qt*32;
    const float* bcol = sBias + qt*32;
    const float* gcol = sG + qt*32;
    float p = 0.f;
    #pragma unroll
    for (int c = 0; c < 32; c += 4) {
        float4 cc = *(const float4*)(crow + c);
        float4 bb = *(const float4*)(bcol + c);
        float4 gg = *(const float4*)(gcol + c);
        p += (cc.x+bb.x)*gg.x + (cc.y+bb.y)*gg.y + (cc.z+bb.z)*gg.z + (cc.w+bb.w)*gg.w;
    }
    p += __shfl_xor_sync(0xFFFFFFFFu, p, 1);
    p += __shfl_xor_sync(0xFFFFFFFFu, p, 2);
    if (qt == 0)
        out[(size_t)(m0+row)*V_ + v] = p + oB[v];
}

// ================= flash-style mma attention ===============================
#define KSTR 12
#define VSTR 132

__global__ __launch_bounds__(256)
void attn_mma(const float* __restrict__ qkv,
              const float* __restrict__ bq, const float* __restrict__ bk,
              const float* __restrict__ bv, float* __restrict__ out) {
    __shared__ uint32_t khi[256*KSTR], klo[256*KSTR];
    __shared__ uint32_t vthi[16*VSTR], vtlo[16*VSTR];

    int bid = blockIdx.x;
    int n = bid & 7, v = (bid >> 3) & 63, b = bid >> 9;
    int tid = threadIdx.x, w = tid >> 5, lane = tid & 31;

    const float* q  = qkv;
    const float* kk = qkv + (size_t)M_*V_*H_;
    const float* vv = qkv + 2*(size_t)M_*V_*H_;
    size_t rstr = (size_t)V_*H_;
    size_t base = ((size_t)(b*S_)*V_ + v)*H_ + n*DH_;
    size_t bofs = (size_t)v*H_ + n*DH_;

    {
        int key = tid;
        const float4* kp = (const float4*)(kk + base + (size_t)key*rstr);
        const float4* vp = (const float4*)(vv + base + (size_t)key*rstr);
        float kr[16], vr[16];
        #pragma unroll
        for (int i = 0; i < 4; i++) {
            float4 a = kp[i], c = vp[i];
            float4 bb = *(const float4*)(bk + bofs + i*4);
            float4 cb = *(const float4*)(bv + bofs + i*4);
            kr[i*4+0]=a.x+bb.x; kr[i*4+1]=a.y+bb.y; kr[i*4+2]=a.z+bb.z; kr[i*4+3]=a.w+bb.w;
            vr[i*4+0]=c.x+cb.x; vr[i*4+1]=c.y+cb.y; vr[i*4+2]=c.z+cb.z; vr[i*4+3]=c.w+cb.w;
        }
        #pragma unroll
        for (int d = 0; d < 8; d++) {
            uint32_t h = pkrn(kr[2*d], kr[2*d+1]);
            khi[key*KSTR + d] = h;
            klo[key*KSTR + d] = pklo(kr[2*d], kr[2*d+1], h);
        }
        unsigned short* vthi16 = (unsigned short*)vthi;
        unsigned short* vtlo16 = (unsigned short*)vtlo;
        #pragma unroll
        for (int c = 0; c < 16; c++) {
            __nv_bfloat16 hb = __float2bfloat16(vr[c]);
            float lo = vr[c] - __bfloat162float(hb);
            __nv_bfloat16 lb = __float2bfloat16(lo);
            vthi16[c*(2*VSTR) + key] = __bfloat16_as_ushort(hb);
            vtlo16[c*(2*VSTR) + key] = __bfloat16_as_ushort(lb);
        }
    }

    int rq = w*32 + (lane >> 2);
    int c2 = (lane & 3) * 2;
    float2 bq0 = make_float2(bq[bofs + c2],     bq[bofs + c2 + 1]);
    float2 bq1 = make_float2(bq[bofs + c2 + 8], bq[bofs + c2 + 9]);
    uint32_t qhi[2][4], qlo[2][4];
    #pragma unroll
    for (int mi = 0; mi < 2; mi++) {
        int rA = rq + mi*16, rB = rA + 8;
        float2 x00 = *(const float2*)(q + base + (size_t)rA*rstr + c2);
        float2 x01 = *(const float2*)(q + base + (size_t)rA*rstr + c2 + 8);
        float2 x10 = *(const float2*)(q + base + (size_t)rB*rstr + c2);
        float2 x11 = *(const float2*)(q + base + (size_t)rB*rstr + c2 + 8);
        x00.x = (x00.x + bq0.x)*0.25f; x00.y = (x00.y + bq0.y)*0.25f;
        x01.x = (x01.x + bq1.x)*0.25f; x01.y = (x01.y + bq1.y)*0.25f;
        x10.x = (x10.x + bq0.x)*0.25f; x10.y = (x10.y + bq0.y)*0.25f;
        x11.x = (x11.x + bq1.x)*0.25f; x11.y = (x11.y + bq1.y)*0.25f;
        qhi[mi][0] = pkrn(x00.x, x00.y); qlo[mi][0] = pklo(x00.x, x00.y, qhi[mi][0]);
        qhi[mi][1] = pkrn(x10.x, x10.y); qlo[mi][1] = pklo(x10.x, x10.y, qhi[mi][1]);
        qhi[mi][2] = pkrn(x01.x, x01.y); qlo[mi][2] = pklo(x01.x, x01.y, qhi[mi][2]);
        qhi[mi][3] = pkrn(x11.x, x11.y); qlo[mi][3] = pklo(x11.x, x11.y, qhi[mi][3]);
    }
    __syncthreads();

    float oacc[2][2][4];
    #pragma unroll
    for (int mi = 0; mi < 2; mi++)
        #pragma unroll
        for (int d = 0; d < 2; d++)
            #pragma unroll
            for (int e = 0; e < 4; e++) oacc[mi][d][e] = 0.f;
    float mrun[2][2] = {{-1e30f,-1e30f},{-1e30f,-1e30f}};
    float lrun[2][2] = {{0.f,0.f},{0.f,0.f}};

    #pragma unroll
    for (int kt = 0; kt < 4; kt++) {
        int kb = kt * 64;
        uint32_t sbh[8][2], sbl[8][2];
        #pragma unroll
        for (int j = 0; j < 8; j++) {
            int key = kb + j*8 + (lane >> 2);
            int ci  = lane & 3;
            sbh[j][0] = khi[key*KSTR + ci];     sbh[j][1] = khi[key*KSTR + ci + 4];
            sbl[j][0] = klo[key*KSTR + ci];     sbl[j][1] = klo[key*KSTR + ci + 4];
        }
        #pragma unroll
        for (int mi = 0; mi < 2; mi++) {
            float C[8][4];
            #pragma unroll
            for (int j = 0; j < 8; j++) { C[j][0]=0.f; C[j][1]=0.f; C[j][2]=0.f; C[j][3]=0.f; }
            #pragma unroll
            for (int j = 0; j < 8; j++) {
                mma16816(C[j], qhi[mi], sbh[j][0], sbh[j][1]);
                mma16816(C[j], qhi[mi], sbl[j][0], sbl[j][1]);
                mma16816(C[j], qlo[mi], sbh[j][0], sbh[j][1]);
            }
            float mA = -1e30f, mB = -1e30f;
            #pragma unroll
            for (int j = 0; j < 8; j++) {
                mA = fmaxf(mA, fmaxf(C[j][0], C[j][1]));
                mB = fmaxf(mB, fmaxf(C[j][2], C[j][3]));
            }
            mA = fmaxf(mA, __shfl_xor_sync(0xFFFFFFFFu, mA, 1));
            mA = fmaxf(mA, __shfl_xor_sync(0xFFFFFFFFu, mA, 2));
            mB = fmaxf(mB, __shfl_xor_sync(0xFFFFFFFFu, mB, 1));
            mB = fmaxf(mB, __shfl_xor_sync(0xFFFFFFFFu, mB, 2));
            float nA = fmaxf(mrun[mi][0], mA), nB = fmaxf(mrun[mi][1], mB);
            float cA = __expf(mrun[mi][0] - nA), cB = __expf(mrun[mi][1] - nB);
            mrun[mi][0] = nA; mrun[mi][1] = nB;
            float sA = 0.f, sB = 0.f;
            #pragma unroll
            for (int j = 0; j < 8; j++) {
                C[j][0] = __expf(C[j][0] - nA); C[j][1] = __expf(C[j][1] - nA);
                C[j][2] = __expf(C[j][2] - nB); C[j][3] = __expf(C[j][3] - nB);
                sA += C[j][0] + C[j][1];
                sB += C[j][2] + C[j][3];
            }
            sA += __shfl_xor_sync(0xFFFFFFFFu, sA, 1);
            sA += __shfl_xor_sync(0xFFFFFFFFu, sA, 2);
            sB += __shfl_xor_sync(0xFFFFFFFFu, sB, 1);
            sB += __shfl_xor_sync(0xFFFFFFFFu, sB, 2);
            lrun[mi][0] = lrun[mi][0]*cA + sA;
            lrun[mi][1] = lrun[mi][1]*cB + sB;
            #pragma unroll
            for (int d = 0; d < 2; d++) {
                oacc[mi][d][0] *= cA; oacc[mi][d][1] *= cA;
                oacc[mi][d][2] *= cB; oacc[mi][d][3] *= cB;
            }
            #pragma unroll
            for (int u = 0; u < 4; u++) {
                uint32_t pa[4], pl[4];
                pa[0] = pkrn(C[2*u][0],   C[2*u][1]);   pl[0] = pklo(C[2*u][0],   C[2*u][1],   pa[0]);
                pa[1] = pkrn(C[2*u][2],   C[2*u][3]);   pl[1] = pklo(C[2*u][2],   C[2*u][3],   pa[1]);
                pa[2] = pkrn(C[2*u+1][0], C[2*u+1][1]); pl[2] = pklo(C[2*u+1][0], C[2*u+1][1], pa[2]);
                pa[3] = pkrn(C[2*u+1][2], C[2*u+1][3]); pl[3] = pklo(C[2*u+1][2], C[2*u+1][3], pa[3]);
                int kb2h = (kb + u*16) >> 1;
                #pragma unroll
                for (int d = 0; d < 2; d++) {
                    int nrow = d*8 + (lane >> 2);
                    uint32_t b0h = vthi[nrow*VSTR + kb2h + (lane & 3)];
                    uint32_t b1h = vthi[nrow*VSTR + kb2h + 4 + (lane & 3)];
                    uint32_t b0l = vtlo[nrow*VSTR + kb2h + (lane & 3)];
                    uint32_t b1l = vtlo[nrow*VSTR + kb2h + 4 + (lane & 3)];
                    mma16816(oacc[mi][d], pa, b0h, b1h);
                    mma16816(oacc[mi][d], pa, b0l, b1l);
                    mma16816(oacc[mi][d], pl, b0h, b1h);
                }
            }
        }
    }

    #pragma unroll
    for (int mi = 0; mi < 2; mi++) {
        float iA = 1.f / lrun[mi][0], iB = 1.f / lrun[mi][1];
        int rA = w*32 + mi*16 + (lane >> 2), rB = rA + 8;
        #pragma unroll
        for (int d = 0; d < 2; d++) {
            *(float2*)(out + base + (size_t)rA*rstr + d*8 + c2) =
                make_float2(oacc[mi][d][0]*iA, oacc[mi][d][1]*iA);
            *(float2*)(out + base + (size_t)rB*rstr + d*8 + c2) =
                make_float2(oacc[mi][d][2]*iB, oacc[mi][d][3]*iB);
        }
    }
}

// ---------------- launch ---------------------------------------------------
extern "C" void kernel_launch(void* const* d_in, const int* in_sizes, int n_in,
                              void* d_out, int out_size) {
    const float* x       = (const float*)d_in[0];
    const float* adjlog  = (const float*)d_in[1];
    const float* var_emb = (const float*)d_in[2];
    const float* temp_emb= (const float*)d_in[3];
    const float* mech_W  = (const float*)d_in[4];
    const float* mech_b  = (const float*)d_in[5];
    const float* ln_g    = (const float*)d_in[6];
    const float* ln_b    = (const float*)d_in[7];
    const float* Wq      = (const float*)d_in[8];
    const float* Wk      = (const float*)d_in[9];
    const float* Wv      = (const float*)d_in[10];
    const float* Wo      = (const float*)d_in[11];
    const float* bq      = (const float*)d_in[12];
    const float* bk      = (const float*)d_in[13];
    const float* bv      = (const float*)d_in[14];
    const float* bo      = (const float*)d_in[15];
    const float* out_W   = (const float*)d_in[16];
    const float* out_b   = (const float*)d_in[17];
    float* out = (float*)d_out;

    float *adjT, *z, *z2, *qkv;
    __nv_bfloat16 *whi, *wlo;
    cudaGetSymbolAddress((void**)&adjT, g_adjT);
    cudaGetSymbolAddress((void**)&z,    g_z);
    cudaGetSymbolAddress((void**)&z2,   g_z2);
    cudaGetSymbolAddress((void**)&qkv,  g_qkv);
    cudaGetSymbolAddress((void**)&whi,  g_whi);
    cudaGetSymbolAddress((void**)&wlo,  g_wlo);

    cudaFuncSetAttribute(fused_mech, cudaFuncAttributeMaxDynamicSharedMemorySize, FGSM);
    cudaFuncSetAttribute(fused_qkv,  cudaFuncAttributeMaxDynamicSharedMemorySize, FGSM);
    cudaFuncSetAttribute(oproj_gemm, cudaFuncAttributeMaxDynamicSharedMemorySize, FGSM);

    prep_adj_kernel<<<(V_*V_*LP1_ + 255)/256, 256>>>(adjlog, adjT);
    prep_w_kernel<<<(7*V_*H_*H_/4 + 255)/256, 256>>>(mech_W, Wq, Wk, Wv, Wo, whi, wlo);
    stage1_kernel<<<M_, 256>>>(x, adjT, var_emb, temp_emb, z);

    dim3 gg(M_/64, V_);
    fused_mech<<<gg, 256, FGSM>>>(z, mech_b, ln_g, ln_b, whi, wlo, z2);
    fused_qkv<<<gg, 256, FGSM>>>(z2, whi, wlo, qkv);
    attn_mma<<<B_*V_*NH_, 256>>>(qkv, bq, bk, bv, z);
    oproj_gemm<<<gg, 256, FGSM>>>(z, whi, wlo, bo, out_W, out_b, out);
}

// round 10
// speedup vs baseline: 1.8404x; 1.0028x over previous
#include <cuda_runtime.h>
#include <cuda_bf16.h>
#include <mma.h>
#include <math.h>
#include <stdint.h>

using namespace nvcuda;

#define B_   4
#define S_   256
#define V_   64
#define LP1_ 11
#define H_   128
#define NH_  8
#define DH_  16
#define NL_  3
#define M_   (B_*S_)   // 1024

// ---------------- scratch (device globals; no allocation) ----------------
__device__ float g_adjT[V_*LP1_*V_];
__device__ float g_z [M_*V_*H_];
__device__ float g_z2[M_*V_*H_];
__device__ float g_qkv[3*M_*V_*H_];
__device__ __align__(16) __nv_bfloat16 g_whi[7*V_*H_*H_];
__device__ __align__(16) __nv_bfloat16 g_wlo[7*V_*H_*H_];

// ---------------- pack helpers --------------------------------------------
__device__ __forceinline__ uint32_t pkrn(float x, float y) {
    __nv_bfloat162 h = __floats2bfloat162_rn(x, y);
    return *(uint32_t*)&h;
}
__device__ __forceinline__ uint32_t pklo(float x, float y, uint32_t hi) {
    __nv_bfloat162 h = *(__nv_bfloat162*)&hi;
    return pkrn(x - __bfloat162float(h.x), y - __bfloat162float(h.y));
}
// truncation split: hi = top16(f) exactly, lo = trunc16(f - hi)
__device__ __forceinline__ void pack_trunc2(float a, float b, uint32_t& h, uint32_t& l) {
    uint32_t ba = __float_as_uint(a), bb = __float_as_uint(b);
    h = __byte_perm(ba, bb, 0x7632);
    float ra = a - __uint_as_float(ba & 0xFFFF0000u);
    float rb = b - __uint_as_float(bb & 0xFFFF0000u);
    l = __byte_perm(__float_as_uint(ra), __float_as_uint(rb), 0x7632);
}

__device__ __forceinline__ uint32_t smem_u32(const void* p) {
    uint32_t a;
    asm("{ .reg .u64 t; cvta.to.shared.u64 t, %1; cvt.u32.u64 %0, t; }" : "=r"(a) : "l"(p));
    return a;
}
__device__ __forceinline__ void cpa16(uint32_t dst, const void* src) {
    asm volatile("cp.async.ca.shared.global [%0], [%1], 16;" :: "r"(dst), "l"(src));
}
#define CP_COMMIT() asm volatile("cp.async.commit_group;" ::: "memory")
#define CP_WAIT(n)  asm volatile("cp.async.wait_group %0;" :: "n"(n) : "memory")

// mma.sync m16n8k16 row.col bf16 -> f32 accumulate in place (attention)
__device__ __forceinline__ void mma16816(float* c, const uint32_t* a, uint32_t b0, uint32_t b1) {
    asm volatile(
        "mma.sync.aligned.m16n8k16.row.col.f32.bf16.bf16.f32 "
        "{%0,%1,%2,%3}, {%4,%5,%6,%7}, {%8,%9}, {%0,%1,%2,%3};\n"
        : "+f"(c[0]), "+f"(c[1]), "+f"(c[2]), "+f"(c[3])
        : "r"(a[0]), "r"(a[1]), "r"(a[2]), "r"(a[3]), "r"(b0), "r"(b1));
}

// ---------------- stage 0: sigmoid + transpose of adjacency --------------
__global__ void prep_adj_kernel(const float* __restrict__ logits, float* __restrict__ adjT) {
    int idx = blockIdx.x * 256 + threadIdx.x;
    if (idx >= V_*V_*LP1_) return;
    int s = idx % V_;
    int r = idx / V_;
    int l = r % LP1_;
    int i = r / LP1_;
    float x = logits[(s*V_ + i)*LP1_ + l];
    adjT[idx] = 1.f / (1.f + __expf(-x));
}

// ---------------- weight split (k-major, rounding split) ------------------
__global__ void prep_w_kernel(const float* __restrict__ mW,
                              const float* __restrict__ Wq, const float* __restrict__ Wk,
                              const float* __restrict__ Wv, const float* __restrict__ Wo,
                              __nv_bfloat16* __restrict__ whi, __nv_bfloat16* __restrict__ wlo) {
    int idx = blockIdx.x * 256 + threadIdx.x;      // one float4
    const int per_mat = H_*H_/4;
    if (idx >= 7*V_*per_mat) return;
    int slotmat = idx / per_mat;
    int within  = idx - slotmat * per_mat;
    int s = slotmat >> 6, v = slotmat & 63;
    const float* src;
    if (s < 3)       src = mW + ((size_t)(v*NL_ + s))*H_*H_;
    else if (s == 3) src = Wq + (size_t)v*H_*H_;
    else if (s == 4) src = Wk + (size_t)v*H_*H_;
    else if (s == 5) src = Wv + (size_t)v*H_*H_;
    else             src = Wo + (size_t)v*H_*H_;
    float4 f = *(const float4*)(src + within*4);
    uint32_t h0 = pkrn(f.x, f.y), h1 = pkrn(f.z, f.w);
    uint32_t l0 = pklo(f.x, f.y, h0), l1 = pklo(f.z, f.w, h1);
    size_t o = (size_t)slotmat*H_*H_ + within*4;
    *(uint2*)(whi + o) = make_uint2(h0, h1);
    *(uint2*)(wlo + o) = make_uint2(l0, l1);
}

// ---------------- stage 1: z[b,t,i,h] -------------------------------------
__global__ __launch_bounds__(256)
void stage1_kernel(const float* __restrict__ x, const float* __restrict__ adjT,
                   const float* __restrict__ var_emb, const float* __restrict__ temp_emb,
                   float* __restrict__ z) {
    int bt = blockIdx.x;
    int b = bt >> 8;
    int t = bt & 255;
    __shared__ float xw[LP1_][V_];
    __shared__ float Am[V_][V_ + 1];
    __shared__ float Bls[V_][LP1_ + 1];
    int tid = threadIdx.x;

    for (int p = tid; p < LP1_*V_; p += 256) {
        int l = p / V_, s = p % V_;
        int tt = t - l;
        xw[l][s] = (tt >= 0) ? x[((size_t)(b*S_ + tt))*V_ + s] : 0.f;
    }
    __syncthreads();

    for (int p = tid; p < V_*V_; p += 256) {
        int i = p >> 6, s = p & 63;
        const float* ap = adjT + (size_t)i*LP1_*V_ + s;
        float a = 0.f;
        #pragma unroll
        for (int l = 0; l < LP1_; l++) a += xw[l][s] * ap[l*V_];
        Am[i][s] = a;
    }
    for (int p = tid; p < V_*LP1_; p += 256) {
        int i = p / LP1_, l = p % LP1_;
        const float* ap = adjT + ((size_t)i*LP1_ + l)*V_;
        float a = 0.f;
        #pragma unroll 8
        for (int s = 0; s < V_; s++) a += xw[l][s] * ap[s];
        Bls[i][l] = a;
    }
    __syncthreads();

    int tx = tid & 15, ty = tid >> 4;
    float acc[4][8];
    #pragma unroll
    for (int r = 0; r < 4; r++)
        #pragma unroll
        for (int c = 0; c < 8; c++) acc[r][c] = 0.f;

    for (int s = 0; s < V_; s++) {
        float a0 = Am[ty*4+0][s], a1 = Am[ty*4+1][s], a2 = Am[ty*4+2][s], a3 = Am[ty*4+3][s];
        const float4* vp = (const float4*)(var_emb + (size_t)s*H_ + tx*8);
        float4 v0 = vp[0], v1 = vp[1];
        float bv[8] = {v0.x,v0.y,v0.z,v0.w,v1.x,v1.y,v1.z,v1.w};
        #pragma unroll
        for (int c = 0; c < 8; c++) {
            acc[0][c] += a0*bv[c]; acc[1][c] += a1*bv[c];
            acc[2][c] += a2*bv[c]; acc[3][c] += a3*bv[c];
        }
    }
    #pragma unroll
    for (int l = 0; l < LP1_; l++) {
        float a0 = Bls[ty*4+0][l], a1 = Bls[ty*4+1][l], a2 = Bls[ty*4+2][l], a3 = Bls[ty*4+3][l];
        const float4* vp = (const float4*)(temp_emb + (size_t)l*H_ + tx*8);
        float4 v0 = vp[0], v1 = vp[1];
        float bv[8] = {v0.x,v0.y,v0.z,v0.w,v1.x,v1.y,v1.z,v1.w};
        #pragma unroll
        for (int c = 0; c < 8; c++) {
            acc[0][c] += a0*bv[c]; acc[1][c] += a1*bv[c];
            acc[2][c] += a2*bv[c]; acc[3][c] += a3*bv[c];
        }
    }
    #pragma unroll
    for (int r = 0; r < 4; r++) {
        int i = ty*4 + r;
        float* zp = z + ((size_t)bt*V_ + i)*H_ + tx*8;
        *(float4*)(zp)   = make_float4(acc[r][0], acc[r][1], acc[r][2], acc[r][3]);
        *(float4*)(zp+4) = make_float4(acc[r][4], acc[r][5], acc[r][6], acc[r][7]);
    }
}

// ========= fused GEMM machinery: BM=64, A full-K smem, W 32-row cp ring ====
// smem budget per CTA: 4608(par) + 34816(A) + 34816(2 W bufs) = 74240 -> 3 CTA/SM
#define FP_PAR   0
#define FSA_HI   4608
#define FSA_LO   (FSA_HI + 17408)
#define FSB0     (FSA_LO + 17408)     // buf0: HI 8704 | LO 8704
#define FSB1     (FSB0 + 17408)       // buf1
#define FGSM     (FSB1 + 17408)       // 74240 B
#define WB_LO    8704                 // lo-half offset within a W buffer
#define FOFF_C   FSB0                 // fp32 C overlaps both W bufs post-mma
#define FLDC     132
#define LD2      136   // bf16 elems per smem tile row

// A tile fill: 64 rows x 128 cols fp32 -> bf16 hi/lo smem (truncation split)
__device__ __forceinline__ void fillA(char* smem, const float* __restrict__ src,
                                      size_t rstr, int tid) {
    __nv_bfloat16* aH = (__nv_bfloat16*)(smem + FSA_HI);
    __nv_bfloat16* aL = (__nv_bfloat16*)(smem + FSA_LO);
    #pragma unroll
    for (int i = 0; i < 8; i++) {
        int f = tid + 256*i;
        int row = f >> 5, c4 = f & 31;
        float4 vv = *(const float4*)(src + (size_t)row*rstr + c4*4);
        uint32_t h0, l0, h1, l1;
        pack_trunc2(vv.x, vv.y, h0, l0);
        pack_trunc2(vv.z, vv.w, h1, l1);
        int off = row*LD2 + c4*4;
        *(uint2*)(aH + off) = make_uint2(h0, h1);
        *(uint2*)(aL + off) = make_uint2(l0, l1);
    }
}

// cp.async one 32-row W chunk (hi+lo) into a W buffer
__device__ __forceinline__ void cpW32(uint32_t sb,
                                      const __nv_bfloat16* __restrict__ hi,
                                      const __nv_bfloat16* __restrict__ lo,
                                      int rowbase, int tid) {
    #pragma unroll
    for (int i = 0; i < 2; i++) {
        int f = tid + 256*i;               // 512 segs of 16B
        int row = f >> 4, seg = f & 15;
        uint32_t so = (uint32_t)row*(LD2*2) + seg*16;
        size_t go = (size_t)(rowbase + row)*H_ + seg*8;
        cpa16(sb + so, hi + go);
        cpa16(sb + WB_LO + so, lo + go);
    }
}

// mma over one 32-k chunk; warp tile 32x32 (wm 2 M halves, wn 4 N quarters)
__device__ __forceinline__ void mma_chunk32(char* smem, int sb, int koff,
    int wm, int wn, wmma::fragment<wmma::accumulator,16,16,16,float> (&acc)[2][2]) {
    const __nv_bfloat16* aH = (const __nv_bfloat16*)(smem + FSA_HI);
    const __nv_bfloat16* aL = (const __nv_bfloat16*)(smem + FSA_LO);
    const __nv_bfloat16* bH = (const __nv_bfloat16*)(smem + sb);
    const __nv_bfloat16* bL = (const __nv_bfloat16*)(smem + sb + WB_LO);
    #pragma unroll
    for (int k0 = 0; k0 < 2; k0++) {
        int ka = koff + k0*16;
        wmma::fragment<wmma::matrix_a, 16, 16, 16, __nv_bfloat16, wmma::row_major> afH[2], afL[2];
        wmma::fragment<wmma::matrix_b, 16, 16, 16, __nv_bfloat16, wmma::row_major> bfH[2], bfL[2];
        #pragma unroll
        for (int mi = 0; mi < 2; mi++) {
            wmma::load_matrix_sync(afH[mi], aH + (size_t)(wm*32 + mi*16)*LD2 + ka, LD2);
            wmma::load_matrix_sync(afL[mi], aL + (size_t)(wm*32 + mi*16)*LD2 + ka, LD2);
        }
        #pragma unroll
        for (int ni = 0; ni < 2; ni++) {
            wmma::load_matrix_sync(bfH[ni], bH + (size_t)(k0*16)*LD2 + wn*32 + ni*16, LD2);
            wmma::load_matrix_sync(bfL[ni], bL + (size_t)(k0*16)*LD2 + wn*32 + ni*16, LD2);
        }
        #pragma unroll
        for (int mi = 0; mi < 2; mi++)
            #pragma unroll
            for (int ni = 0; ni < 2; ni++) {
                wmma::mma_sync(acc[mi][ni], afH[mi], bfH[ni], acc[mi][ni]);
                wmma::mma_sync(acc[mi][ni], afH[mi], bfL[ni], acc[mi][ni]);
                wmma::mma_sync(acc[mi][ni], afL[mi], bfH[ni], acc[mi][ni]);
            }
    }
}

// run one layer: 4-chunk cp.async ring + mma; C left in smem.
__device__ __forceinline__ void run_layer(char* smem, uint32_t sbase,
    const __nv_bfloat16* whi, const __nv_bfloat16* wlo, int wm, int wn, int tid,
    wmma::fragment<wmma::accumulator,16,16,16,float> (&acc)[2][2]) {
    #pragma unroll
    for (int mi = 0; mi < 2; mi++)
        #pragma unroll
        for (int ni = 0; ni < 2; ni++) wmma::fill_fragment(acc[mi][ni], 0.f);
    const int bufs[2] = {FSB0, FSB1};
    cpW32(sbase + FSB0, whi, wlo, 0, tid);
    CP_COMMIT();
    #pragma unroll
    for (int c = 0; c < 4; c++) {
        if (c < 3) {
            cpW32(sbase + bufs[(c+1)&1], whi, wlo, (c+1)*32, tid);
            CP_COMMIT();
            CP_WAIT(1);
        } else {
            CP_WAIT(0);
        }
        __syncthreads();
        mma_chunk32(smem, bufs[c&1], c*32, wm, wn, acc);
        __syncthreads();
    }
    float* Cs = (float*)(smem + FOFF_C);
    #pragma unroll
    for (int mi = 0; mi < 2; mi++)
        #pragma unroll
        for (int ni = 0; ni < 2; ni++)
            wmma::store_matrix_sync(Cs + (size_t)(wm*32 + mi*16)*FLDC + wn*32 + ni*16,
                                    acc[mi][ni], FLDC, wmma::mem_row_major);
    __syncthreads();
}

// ---------------- fused 3-layer mech chain ---------------------------------
__global__ __launch_bounds__(256, 3)
void fused_mech(const float* __restrict__ z, const float* __restrict__ mech_b,
                const float* __restrict__ lng, const float* __restrict__ lnb,
                const __nv_bfloat16* __restrict__ whi, const __nv_bfloat16* __restrict__ wlo,
                float* __restrict__ outz) {
    extern __shared__ char smem[];
    uint32_t sbase = smem_u32(smem);
    int tid = threadIdx.x;
    int v = blockIdx.y, m0 = blockIdx.x * 64;
    int w = tid >> 5, wm = w & 1, wn = w >> 1;

    float* sBias = (float*)(smem + FP_PAR);
    float* sG    = sBias + 3*128;
    float* sBeta = sG + 3*128;
    if (tid < 128) {
        #pragma unroll
        for (int li = 0; li < 3; li++) {
            sBias[li*128 + tid] = mech_b[(size_t)v*NL_*H_ + li*H_ + tid];
            sG[li*128 + tid]    = lng  [(size_t)v*NL_*H_ + li*H_ + tid];
            sBeta[li*128 + tid] = lnb  [(size_t)v*NL_*H_ + li*H_ + tid];
        }
    }
    fillA(smem, z + ((size_t)m0*V_ + v)*H_, (size_t)V_*H_, tid);
    __syncthreads();

    wmma::fragment<wmma::accumulator,16,16,16,float> acc[2][2];
    int row = tid >> 2, qt = tid & 3;
    float* Cs = (float*)(smem + FOFF_C);
    __nv_bfloat16* aH = (__nv_bfloat16*)(smem + FSA_HI);
    __nv_bfloat16* aL = (__nv_bfloat16*)(smem + FSA_LO);

    #pragma unroll
    for (int li = 0; li < 3; li++) {
        const __nv_bfloat16* wh = whi + ((size_t)li*V_ + v)*H_*H_;
        const __nv_bfloat16* wl = wlo + ((size_t)li*V_ + v)*H_*H_;
        run_layer(smem, sbase, wh, wl, wm, wn, tid, acc);

        // epilogue: quarter-row per thread, LN + GELU
        const float* crow = Cs + (size_t)row*FLDC + qt*32;
        const float* bcol = sBias + li*128 + qt*32;
        float s = 0.f, q = 0.f;
        #pragma unroll
        for (int c = 0; c < 32; c += 4) {
            float4 cc = *(const float4*)(crow + c);
            float4 bb = *(const float4*)(bcol + c);
            float y0 = cc.x+bb.x, y1 = cc.y+bb.y, y2 = cc.z+bb.z, y3 = cc.w+bb.w;
            s += y0 + y1 + y2 + y3;
            q += y0*y0 + y1*y1 + y2*y2 + y3*y3;
        }
        s += __shfl_xor_sync(0xFFFFFFFFu, s, 1);
        q += __shfl_xor_sync(0xFFFFFFFFu, q, 1);
        s += __shfl_xor_sync(0xFFFFFFFFu, s, 2);
        q += __shfl_xor_sync(0xFFFFFFFFu, q, 2);
        float mean = s * (1.f/128.f);
        float var  = q * (1.f/128.f) - mean*mean;
        float rstd = rsqrtf(var + 1e-5f);
        const float* gcol = sG + li*128 + qt*32;
        const float* lcol = sBeta + li*128 + qt*32;
        #pragma unroll
        for (int c = 0; c < 32; c += 4) {
            float4 cc = *(const float4*)(crow + c);
            float4 bb = *(const float4*)(bcol + c);
            float4 gg = *(const float4*)(gcol + c);
            float4 ll = *(const float4*)(lcol + c);
            float yv[4] = {cc.x+bb.x, cc.y+bb.y, cc.z+bb.z, cc.w+bb.w};
            float gv[4] = {gg.x, gg.y, gg.z, gg.w};
            float lv[4] = {ll.x, ll.y, ll.z, ll.w};
            float o4[4];
            #pragma unroll
            for (int j = 0; j < 4; j++) {
                float t2 = (yv[j] - mean) * rstd * gv[j] + lv[j];
                o4[j] = 0.5f * t2 * (1.f + erff(t2 * 0.7071067811865476f));
            }
            if (li < 2) {
                uint32_t h0, l0, h1, l1;
                pack_trunc2(o4[0], o4[1], h0, l0);
                pack_trunc2(o4[2], o4[3], h1, l1);
                int off = row*LD2 + qt*32 + c;
                *(uint2*)(aH + off) = make_uint2(h0, h1);
                *(uint2*)(aL + off) = make_uint2(l0, l1);
            } else {
                *(float4*)(outz + ((size_t)(m0+row)*V_ + v)*H_ + qt*32 + c) =
                    make_float4(o4[0], o4[1], o4[2], o4[3]);
            }
        }
        __syncthreads();
    }
}

// ---------------- fused QKV (A converted once; 3 weight slots) -------------
__global__ __launch_bounds__(256, 3)
void fused_qkv(const float* __restrict__ z2,
               const __nv_bfloat16* __restrict__ whi, const __nv_bfloat16* __restrict__ wlo,
               float* __restrict__ qkv) {
    extern __shared__ char smem[];
    uint32_t sbase = smem_u32(smem);
    int tid = threadIdx.x;
    int v = blockIdx.y, m0 = blockIdx.x * 64;
    int w = tid >> 5, wm = w & 1, wn = w >> 1;

    fillA(smem, z2 + ((size_t)m0*V_ + v)*H_, (size_t)V_*H_, tid);
    __syncthreads();

    wmma::fragment<wmma::accumulator,16,16,16,float> acc[2][2];
    int row = tid >> 2, qt = tid & 3;
    float* Cs = (float*)(smem + FOFF_C);

    #pragma unroll
    for (int zi = 0; zi < 3; zi++) {
        const __nv_bfloat16* wh = whi + ((size_t)(3+zi)*V_ + v)*H_*H_;
        const __nv_bfloat16* wl = wlo + ((size_t)(3+zi)*V_ + v)*H_*H_;
        run_layer(smem, sbase, wh, wl, wm, wn, tid, acc);
        float* orow = qkv + (size_t)zi*M_*V_*H_ + ((size_t)(m0+row)*V_ + v)*H_ + qt*32;
        const float* crow = Cs + (size_t)row*FLDC + qt*32;
        #pragma unroll
        for (int c = 0; c < 32; c += 4)
            *(float4*)(orow + c) = *(const float4*)(crow + c);
        __syncthreads();
    }
}

// ---------------- O-proj + output head -------------------------------------
__global__ __launch_bounds__(256, 3)
void oproj_gemm(const float* __restrict__ att,
                const __nv_bfloat16* __restrict__ whi, const __nv_bfloat16* __restrict__ wlo,
                const float* __restrict__ bo, const float* __restrict__ oW,
                const float* __restrict__ oB, float* __restrict__ out) {
    extern __shared__ char smem[];
    uint32_t sbase = smem_u32(smem);
    int tid = threadIdx.x;
    int v = blockIdx.y, m0 = blockIdx.x * 64;
    int w = tid >> 5, wm = w & 1, wn = w >> 1;

    float* sBias = (float*)(smem + FP_PAR);
    float* sG    = sBias + 3*128;
    if (tid < 128) {
        sBias[tid] = bo[(size_t)v*H_ + tid];
        sG[tid]    = oW[(size_t)v*H_ + tid];
    }
    fillA(smem, att + ((size_t)m0*V_ + v)*H_, (size_t)V_*H_, tid);
    __syncthreads();

    wmma::fragment<wmma::accumulator,16,16,16,float> acc[2][2];
    const __nv_bfloat16* wh = whi + ((size_t)6*V_ + v)*H_*H_;
    const __nv_bfloat16* wl = wlo + ((size_t)6*V_ + v)*H_*H_;
    run_layer(smem, sbase, wh, wl, wm, wn, tid, acc);

    int row = tid >> 2, qt = tid & 3;
    float* Cs = (float*)(smem + FOFF_C);
    const float* crow = Cs + (size_t)row*FLDC + qt*32;
    const float* bcol = sBias + qt*32;
    const float* gcol = sG + qt*32;
    float p = 0.f;
    #pragma unroll
    for (int c = 0; c < 32; c += 4) {
        float4 cc = *(const float4*)(crow + c);
        float4 bb = *(const float4*)(bcol + c);
        float4 gg = *(const float4*)(gcol + c);
        p += (cc.x+bb.x)*gg.x + (cc.y+bb.y)*gg.y + (cc.z+bb.z)*gg.z + (cc.w+bb.w)*gg.w;
    }
    p += __shfl_xor_sync(0xFFFFFFFFu, p, 1);
    p += __shfl_xor_sync(0xFFFFFFFFu, p, 2);
    if (qt == 0)
        out[(size_t)(m0+row)*V_ + v] = p + oB[v];
}

// ================= flash-style mma attention ===============================
#define KSTR 12
#define VSTR 132

__global__ __launch_bounds__(256)
void attn_mma(const float* __restrict__ qkv,
              const float* __restrict__ bq, const float* __restrict__ bk,
              const float* __restrict__ bv, float* __restrict__ out) {
    __shared__ uint32_t khi[256*KSTR], klo[256*KSTR];
    __shared__ uint32_t vthi[16*VSTR], vtlo[16*VSTR];

    int bid = blockIdx.x;
    int n = bid & 7, v = (bid >> 3) & 63, b = bid >> 9;
    int tid = threadIdx.x, w = tid >> 5, lane = tid & 31;

    const float* q  = qkv;
    const float* kk = qkv + (size_t)M_*V_*H_;
    const float* vv = qkv + 2*(size_t)M_*V_*H_;
    size_t rstr = (size_t)V_*H_;
    size_t base = ((size_t)(b*S_)*V_ + v)*H_ + n*DH_;
    size_t bofs = (size_t)v*H_ + n*DH_;

    {
        int key = tid;
        const float4* kp = (const float4*)(kk + base + (size_t)key*rstr);
        const float4* vp = (const float4*)(vv + base + (size_t)key*rstr);
        float kr[16], vr[16];
        #pragma unroll
        for (int i = 0; i < 4; i++) {
            float4 a = kp[i], c = vp[i];
            float4 bb = *(const float4*)(bk + bofs + i*4);
            float4 cb = *(const float4*)(bv + bofs + i*4);
            kr[i*4+0]=a.x+bb.x; kr[i*4+1]=a.y+bb.y; kr[i*4+2]=a.z+bb.z; kr[i*4+3]=a.w+bb.w;
            vr[i*4+0]=c.x+cb.x; vr[i*4+1]=c.y+cb.y; vr[i*4+2]=c.z+cb.z; vr[i*4+3]=c.w+cb.w;
        }
        #pragma unroll
        for (int d = 0; d < 8; d++) {
            uint32_t h = pkrn(kr[2*d], kr[2*d+1]);
            khi[key*KSTR + d] = h;
            klo[key*KSTR + d] = pklo(kr[2*d], kr[2*d+1], h);
        }
        unsigned short* vthi16 = (unsigned short*)vthi;
        unsigned short* vtlo16 = (unsigned short*)vtlo;
        #pragma unroll
        for (int c = 0; c < 16; c++) {
            __nv_bfloat16 hb = __float2bfloat16(vr[c]);
            float lo = vr[c] - __bfloat162float(hb);
            __nv_bfloat16 lb = __float2bfloat16(lo);
            vthi16[c*(2*VSTR) + key] = __bfloat16_as_ushort(hb);
            vtlo16[c*(2*VSTR) + key] = __bfloat16_as_ushort(lb);
        }
    }

    int rq = w*32 + (lane >> 2);
    int c2 = (lane & 3) * 2;
    float2 bq0 = make_float2(bq[bofs + c2],     bq[bofs + c2 + 1]);
    float2 bq1 = make_float2(bq[bofs + c2 + 8], bq[bofs + c2 + 9]);
    uint32_t qhi[2][4], qlo[2][4];
    #pragma unroll
    for (int mi = 0; mi < 2; mi++) {
        int rA = rq + mi*16, rB = rA + 8;
        float2 x00 = *(const float2*)(q + base + (size_t)rA*rstr + c2);
        float2 x01 = *(const float2*)(q + base + (size_t)rA*rstr + c2 + 8);
        float2 x10 = *(const float2*)(q + base + (size_t)rB*rstr + c2);
        float2 x11 = *(const float2*)(q + base + (size_t)rB*rstr + c2 + 8);
        x00.x = (x00.x + bq0.x)*0.25f; x00.y = (x00.y + bq0.y)*0.25f;
        x01.x = (x01.x + bq1.x)*0.25f; x01.y = (x01.y + bq1.y)*0.25f;
        x10.x = (x10.x + bq0.x)*0.25f; x10.y = (x10.y + bq0.y)*0.25f;
        x11.x = (x11.x + bq1.x)*0.25f; x11.y = (x11.y + bq1.y)*0.25f;
        qhi[mi][0] = pkrn(x00.x, x00.y); qlo[mi][0] = pklo(x00.x, x00.y, qhi[mi][0]);
        qhi[mi][1] = pkrn(x10.x, x10.y); qlo[mi][1] = pklo(x10.x, x10.y, qhi[mi][1]);
        qhi[mi][2] = pkrn(x01.x, x01.y); qlo[mi][2] = pklo(x01.x, x01.y, qhi[mi][2]);
        qhi[mi][3] = pkrn(x11.x, x11.y); qlo[mi][3] = pklo(x11.x, x11.y, qhi[mi][3]);
    }
    __syncthreads();

    float oacc[2][2][4];
    #pragma unroll
    for (int mi = 0; mi < 2; mi++)
        #pragma unroll
        for (int d = 0; d < 2; d++)
            #pragma unroll
            for (int e = 0; e < 4; e++) oacc[mi][d][e] = 0.f;
    float mrun[2][2] = {{-1e30f,-1e30f},{-1e30f,-1e30f}};
    float lrun[2][2] = {{0.f,0.f},{0.f,0.f}};

    #pragma unroll
    for (int kt = 0; kt < 4; kt++) {
        int kb = kt * 64;
        uint32_t sbh[8][2], sbl[8][2];
        #pragma unroll
        for (int j = 0; j < 8; j++) {
            int key = kb + j*8 + (lane >> 2);
            int ci  = lane & 3;
            sbh[j][0] = khi[key*KSTR + ci];     sbh[j][1] = khi[key*KSTR + ci + 4];
            sbl[j][0] = klo[key*KSTR + ci];     sbl[j][1] = klo[key*KSTR + ci + 4];
        }
        #pragma unroll
        for (int mi = 0; mi < 2; mi++) {
            float C[8][4];
            #pragma unroll
            for (int j = 0; j < 8; j++) { C[j][0]=0.f; C[j][1]=0.f; C[j][2]=0.f; C[j][3]=0.f; }
            #pragma unroll
            for (int j = 0; j < 8; j++) {
                mma16816(C[j], qhi[mi], sbh[j][0], sbh[j][1]);
                mma16816(C[j], qhi[mi], sbl[j][0], sbl[j][1]);
                mma16816(C[j], qlo[mi], sbh[j][0], sbh[j][1]);
            }
            float mA = -1e30f, mB = -1e30f;
            #pragma unroll
            for (int j = 0; j < 8; j++) {
                mA = fmaxf(mA, fmaxf(C[j][0], C[j][1]));
                mB = fmaxf(mB, fmaxf(C[j][2], C[j][3]));
            }
            mA = fmaxf(mA, __shfl_xor_sync(0xFFFFFFFFu, mA, 1));
            mA = fmaxf(mA, __shfl_xor_sync(0xFFFFFFFFu, mA, 2));
            mB = fmaxf(mB, __shfl_xor_sync(0xFFFFFFFFu, mB, 1));
            mB = fmaxf(mB, __shfl_xor_sync(0xFFFFFFFFu, mB, 2));
            float nA = fmaxf(mrun[mi][0], mA), nB = fmaxf(mrun[mi][1], mB);
            float cA = __expf(mrun[mi][0] - nA), cB = __expf(mrun[mi][1] - nB);
            mrun[mi][0] = nA; mrun[mi][1] = nB;
            float sA = 0.f, sB = 0.f;
            #pragma unroll
            for (int j = 0; j < 8; j++) {
                C[j][0] = __expf(C[j][0] - nA); C[j][1] = __expf(C[j][1] - nA);
                C[j][2] = __expf(C[j][2] - nB); C[j][3] = __expf(C[j][3] - nB);
                sA += C[j][0] + C[j][1];
                sB += C[j][2] + C[j][3];
            }
            sA += __shfl_xor_sync(0xFFFFFFFFu, sA, 1);
            sA += __shfl_xor_sync(0xFFFFFFFFu, sA, 2);
            sB += __shfl_xor_sync(0xFFFFFFFFu, sB, 1);
            sB += __shfl_xor_sync(0xFFFFFFFFu, sB, 2);
            lrun[mi][0] = lrun[mi][0]*cA + sA;
            lrun[mi][1] = lrun[mi][1]*cB + sB;
            #pragma unroll
            for (int d = 0; d < 2; d++) {
                oacc[mi][d][0] *= cA; oacc[mi][d][1] *= cA;
                oacc[mi][d][2] *= cB; oacc[mi][d][3] *= cB;
            }
            #pragma unroll
            for (int u = 0; u < 4; u++) {
                uint32_t pa[4], pl[4];
                pa[0] = pkrn(C[2*u][0],   C[2*u][1]);   pl[0] = pklo(C[2*u][0],   C[2*u][1],   pa[0]);
                pa[1] = pkrn(C[2*u][2],   C[2*u][3]);   pl[1] = pklo(C[2*u][2],   C[2*u][3],   pa[1]);
                pa[2] = pkrn(C[2*u+1][0], C[2*u+1][1]); pl[2] = pklo(C[2*u+1][0], C[2*u+1][1], pa[2]);
                pa[3] = pkrn(C[2*u+1][2], C[2*u+1][3]); pl[3] = pklo(C[2*u+1][2], C[2*u+1][3], pa[3]);
                int kb2h = (kb + u*16) >> 1;
                #pragma unroll
                for (int d = 0; d < 2; d++) {
                    int nrow = d*8 + (lane >> 2);
                    uint32_t b0h = vthi[nrow*VSTR + kb2h + (lane & 3)];
                    uint32_t b1h = vthi[nrow*VSTR + kb2h + 4 + (lane & 3)];
                    uint32_t b0l = vtlo[nrow*VSTR + kb2h + (lane & 3)];
                    uint32_t b1l = vtlo[nrow*VSTR + kb2h + 4 + (lane & 3)];
                    mma16816(oacc[mi][d], pa, b0h, b1h);
                    mma16816(oacc[mi][d], pa, b0l, b1l);
                    mma16816(oacc[mi][d], pl, b0h, b1h);
                }
            }
        }
    }

    #pragma unroll
    for (int mi = 0; mi < 2; mi++) {
        float iA = 1.f / lrun[mi][0], iB = 1.f / lrun[mi][1];
        int rA = w*32 + mi*16 + (lane >> 2), rB = rA + 8;
        #pragma unroll
        for (int d = 0; d < 2; d++) {
            *(float2*)(out + base + (size_t)rA*rstr + d*8 + c2) =
                make_float2(oacc[mi][d][0]*iA, oacc[mi][d][1]*iA);
            *(float2*)(out + base + (size_t)rB*rstr + d*8 + c2) =
                make_float2(oacc[mi][d][2]*iB, oacc[mi][d][3]*iB);
        }
    }
}

// ---------------- launch ---------------------------------------------------
extern "C" void kernel_launch(void* const* d_in, const int* in_sizes, int n_in,
                              void* d_out, int out_size) {
    const float* x       = (const float*)d_in[0];
    const float* adjlog  = (const float*)d_in[1];
    const float* var_emb = (const float*)d_in[2];
    const float* temp_emb= (const float*)d_in[3];
    const float* mech_W  = (const float*)d_in[4];
    const float* mech_b  = (const float*)d_in[5];
    const float* ln_g    = (const float*)d_in[6];
    const float* ln_b    = (const float*)d_in[7];
    const float* Wq      = (const float*)d_in[8];
    const float* Wk      = (const float*)d_in[9];
    const float* Wv      = (const float*)d_in[10];
    const float* Wo      = (const float*)d_in[11];
    const float* bq      = (const float*)d_in[12];
    const float* bk      = (const float*)d_in[13];
    const float* bv      = (const float*)d_in[14];
    const float* bo      = (const float*)d_in[15];
    const float* out_W   = (const float*)d_in[16];
    const float* out_b   = (const float*)d_in[17];
    float* out = (float*)d_out;

    float *adjT, *z, *z2, *qkv;
    __nv_bfloat16 *whi, *wlo;
    cudaGetSymbolAddress((void**)&adjT, g_adjT);
    cudaGetSymbolAddress((void**)&z,    g_z);
    cudaGetSymbolAddress((void**)&z2,   g_z2);
    cudaGetSymbolAddress((void**)&qkv,  g_qkv);
    cudaGetSymbolAddress((void**)&whi,  g_whi);
    cudaGetSymbolAddress((void**)&wlo,  g_wlo);

    cudaFuncSetAttribute(fused_mech, cudaFuncAttributeMaxDynamicSharedMemorySize, FGSM);
    cudaFuncSetAttribute(fused_qkv,  cudaFuncAttributeMaxDynamicSharedMemorySize, FGSM);
    cudaFuncSetAttribute(oproj_gemm, cudaFuncAttributeMaxDynamicSharedMemorySize, FGSM);

    prep_adj_kernel<<<(V_*V_*LP1_ + 255)/256, 256>>>(adjlog, adjT);
    prep_w_kernel<<<(7*V_*H_*H_/4 + 255)/256, 256>>>(mech_W, Wq, Wk, Wv, Wo, whi, wlo);
    stage1_kernel<<<M_, 256>>>(x, adjT, var_emb, temp_emb, z);

    dim3 gg(M_/64, V_);
    fused_mech<<<gg, 256, FGSM>>>(z, mech_b, ln_g, ln_b, whi, wlo, z2);
    fused_qkv<<<gg, 256, FGSM>>>(z2, whi, wlo, qkv);
    attn_mma<<<B_*V_*NH_, 256>>>(qkv, bq, bk, bv, z);
    oproj_gemm<<<gg, 256, FGSM>>>(z, whi, wlo, bo, out_W, out_b, out);
}